// round 9
// baseline (speedup 1.0000x reference)
#include <cuda_runtime.h>
#include <cstdint>
#include <math.h>
#include <mma.h>

using namespace nvcuda;

// Problem constants
#define BB 2
#define SS 2048
#define HH 12
#define DHD 64
#define DD 768
#define DFF 3072
#define MM (BB*SS)
#define Y_ELEMS ((size_t)BB*SS*DD)

// ---------------- scratch (device globals) ---------------------------------
__device__ float g_q [BB*HH*SS*DHD];
__device__ float g_k [BB*HH*SS*DHD];
__device__ float g_v [BB*HH*SS*DHD];
__device__ float g_av[BB*SS*DD];
__device__ float g_ao[BB*SS*DD];
__device__ float g_h [BB*SS*DD];
__device__ float g_f1[BB*SS*DFF];
__device__ float g_f2[BB*SS*DD];

__device__ __forceinline__ void cp_async16(unsigned int dst, const void* src) {
    asm volatile("cp.async.cg.shared.global [%0], [%1], 16;\n" :: "r"(dst), "l"(src));
}
__device__ __forceinline__ void cp_commit() {
    asm volatile("cp.async.commit_group;\n");
}
__device__ __forceinline__ void cp_wait0() {
    asm volatile("cp.async.wait_group 0;\n");
}

// ============  tf32 NT GEMM, 2-stage cp.async, 2 CTAs/SM  ==================
// Raw fp32 in smem; tf32 HMMA truncates mantissa in hardware.
#define GLD 36
#define GBUF (128*GLD)
#define GSTG 2
#define GEMM_SMEM_BYTES (GSTG*2*GBUF*4)   // 73,728 B -> 2 CTAs/SM

// C[m,n] = sum_k A[m,k]*B[n,k]
template<int MODE>
__device__ __forceinline__ void gemm_body(const float* __restrict__ A,
                                          const float* __restrict__ B,
                                          float* __restrict__ C,
                                          int N, int K, int m0, int n0)
{
    extern __shared__ float gsm[];
    float* As = gsm;                    // [2][128][36]
    float* Bs = gsm + GSTG*GBUF;        // [2][128][36]

    const int tid  = threadIdx.x;
    const int warp = tid >> 5;
    const int wm   = warp & 1;
    const int wn   = warp >> 1;
    const int lr   = tid >> 3;          // 0..31
    const int lc4  = (tid & 7) * 4;     // 0..28

    const unsigned int as_s = (unsigned int)__cvta_generic_to_shared(As);
    const unsigned int bs_s = (unsigned int)__cvta_generic_to_shared(Bs);

    wmma::fragment<wmma::accumulator, 16, 16, 8, float> c[4][2];
    #pragma unroll
    for (int i = 0; i < 4; i++)
        #pragma unroll
        for (int j = 0; j < 2; j++)
            wmma::fill_fragment(c[i][j], 0.0f);

    const int T = K >> 5;

    auto issue = [&](int t) {
        const int k0 = t << 5;
        const unsigned int soff = (unsigned int)((t & 1) * GBUF * 4);
        #pragma unroll
        for (int i = 0; i < 4; i++) {
            int row = lr + i * 32;
            cp_async16(as_s + soff + (unsigned int)((row * GLD + lc4) * 4),
                       &A[(size_t)(m0 + row) * K + k0 + lc4]);
            cp_async16(bs_s + soff + (unsigned int)((row * GLD + lc4) * 4),
                       &B[(size_t)(n0 + row) * K + k0 + lc4]);
        }
        cp_commit();
    };

    issue(0);

    for (int t = 0; t < T; t++) {
        cp_wait0();
        __syncthreads();
        if (t + 1 < T) issue(t + 1);     // copy t+1 overlaps compute t

        const int cur = (t & 1) * GBUF;
        #pragma unroll
        for (int kk = 0; kk < 32; kk += 8) {
            wmma::fragment<wmma::matrix_a, 16, 16, 8, wmma::precision::tf32, wmma::row_major> a[4];
            wmma::fragment<wmma::matrix_b, 16, 16, 8, wmma::precision::tf32, wmma::col_major> b[2];
            #pragma unroll
            for (int i = 0; i < 4; i++)
                wmma::load_matrix_sync(a[i], &As[cur + (wm * 64 + i * 16) * GLD + kk], GLD);
            #pragma unroll
            for (int j = 0; j < 2; j++)
                wmma::load_matrix_sync(b[j], &Bs[cur + (wn * 32 + j * 16) * GLD + kk], GLD);
            #pragma unroll
            for (int i = 0; i < 4; i++)
                #pragma unroll
                for (int j = 0; j < 2; j++)
                    wmma::mma_sync(c[i][j], a[i], b[j], c[i][j]);
        }
        __syncthreads();
    }

    #pragma unroll
    for (int i = 0; i < 4; i++) {
        int m = m0 + wm * 64 + i * 16;
        #pragma unroll
        for (int j = 0; j < 2; j++) {
            int n = n0 + wn * 32 + j * 16;
            if (MODE == 3) {
                int bidx = m >> 11, s = m & 2047;
                int h = n >> 6, dh = n & 63;
                float* dst = C + (((size_t)(bidx * HH + h)) * SS + s) * DHD + dh;
                wmma::store_matrix_sync(dst, c[i][j], DHD, wmma::mem_row_major);
            } else {
                wmma::store_matrix_sync(C + (size_t)m * N + n, c[i][j], N, wmma::mem_row_major);
            }
        }
    }
}

__global__ void __launch_bounds__(256, 2)
gemm_tc_nt(const float* __restrict__ A, const float* __restrict__ B,
           float* __restrict__ C, int N, int K)
{
    gemm_body<0>(A, B, C, N, K, blockIdx.y * 128, blockIdx.x * 128);
}

// merged QKV: grid.z selects (W, out) pair; head-split store
__global__ void __launch_bounds__(256, 2)
qkv_gemm(const float* __restrict__ X,
         const float* __restrict__ Wq, const float* __restrict__ Wk,
         const float* __restrict__ Wv,
         float* __restrict__ Qo, float* __restrict__ Ko, float* __restrict__ Vo)
{
    const float* B = (blockIdx.z == 0) ? Wq : (blockIdx.z == 1) ? Wk : Wv;
    float*       C = (blockIdx.z == 0) ? Qo : (blockIdx.z == 1) ? Ko : Vo;
    gemm_body<3>(X, B, C, DD, DD, blockIdx.y * 128, blockIdx.x * 128);
}

// ==============  fused flash attention, cp.async pipelined  ================
#define ATT_LDQ 68
#define QBUF (128*ATT_LDQ)
#define ATT_LDS 132
#define ATT_SMEM_FLOATS (4*QBUF + 128*ATT_LDS + 128)   // Q,K,V[2],S,ls

__global__ void __launch_bounds__(512, 1)
attn_fused(const float* __restrict__ Q, const float* __restrict__ K,
           const float* __restrict__ V, float* __restrict__ P,
           float* __restrict__ AV)
{
    extern __shared__ float sm[];
    float* Qs = sm;                 // [128][68]
    float* Ks = Qs + QBUF;          // [128][68]
    float* Vs = Ks + QBUF;          // [2][128][68]
    float* Ss = Vs + 2*QBUF;        // [128][132]
    float* ls = Ss + 128 * ATT_LDS; // [128]

    const int bh  = blockIdx.y;
    const int qt  = gridDim.x - 1 - blockIdx.x;
    const int m0  = qt * 128;
    const int tid = threadIdx.x;
    const int warp = tid >> 5;
    const int wm = warp & 3;
    const int wn = warp >> 2;

    const float* Qb = Q + ((size_t)bh * SS + m0) * DHD;
    const float* Kb = K + (size_t)bh * SS * DHD;
    const float* Vb = V + (size_t)bh * SS * DHD;
    float* Pb = P + ((size_t)bh * SS + m0) * SS;

    const int pr  = tid >> 4;
    const int pc4 = (tid & 15) * 4;
    const unsigned int ks_s = (unsigned int)__cvta_generic_to_shared(Ks);
    const unsigned int vs_s = (unsigned int)__cvta_generic_to_shared(Vs);

    // load Q tile, pre-scaled by 1/8
    for (int i = tid; i < 128 * 16; i += 512) {
        int r = i >> 4, c4 = (i & 15) * 4;
        float4 v = *(const float4*)&Qb[(size_t)r * DHD + c4];
        v.x *= 0.125f; v.y *= 0.125f; v.z *= 0.125f; v.w *= 0.125f;
        *(float4*)&Qs[r * ATT_LDQ + c4] = v;
    }
    if (tid < 128) ls[tid] = 0.0f;

    // issue copies for kt = 0
    #pragma unroll
    for (int u = 0; u < 4; u++) {
        int r = pr + u * 32;
        cp_async16(ks_s + (r * ATT_LDQ + pc4) * 4, &Kb[(size_t)r * DHD + pc4]);
        cp_async16(vs_s + (r * ATT_LDQ + pc4) * 4, &Vb[(size_t)r * DHD + pc4]);
    }
    cp_commit();

    wmma::fragment<wmma::accumulator, 16, 16, 8, float> co[2];
    #pragma unroll
    for (int i = 0; i < 2; i++) wmma::fill_fragment(co[i], 0.0f);

    for (int kt = 0; kt <= qt; kt++) {
        const int cur = (kt & 1) * QBUF;
        cp_wait0();
        __syncthreads();

        // S = Qs @ Ks^T  (warp tile 32x32)
        wmma::fragment<wmma::accumulator, 16, 16, 8, float> cs[2][2];
        #pragma unroll
        for (int i = 0; i < 2; i++)
            #pragma unroll
            for (int j = 0; j < 2; j++)
                wmma::fill_fragment(cs[i][j], 0.0f);

        #pragma unroll
        for (int kk = 0; kk < 64; kk += 8) {
            wmma::fragment<wmma::matrix_a, 16, 16, 8, wmma::precision::tf32, wmma::row_major> a[2];
            wmma::fragment<wmma::matrix_b, 16, 16, 8, wmma::precision::tf32, wmma::col_major> b[2];
            #pragma unroll
            for (int i = 0; i < 2; i++)
                wmma::load_matrix_sync(a[i], &Qs[(wm * 32 + i * 16) * ATT_LDQ + kk], ATT_LDQ);
            #pragma unroll
            for (int j = 0; j < 2; j++)
                wmma::load_matrix_sync(b[j], &Ks[(wn * 32 + j * 16) * ATT_LDQ + kk], ATT_LDQ);
            #pragma unroll
            for (int i = 0; i < 2; i++)
                #pragma unroll
                for (int j = 0; j < 2; j++)
                    wmma::mma_sync(cs[i][j], a[i], b[j], cs[i][j]);
        }
        #pragma unroll
        for (int i = 0; i < 2; i++)
            #pragma unroll
            for (int j = 0; j < 2; j++)
                wmma::store_matrix_sync(&Ss[(wm * 32 + i * 16) * ATT_LDS + wn * 32 + j * 16],
                                        cs[i][j], ATT_LDS, wmma::mem_row_major);
        __syncthreads();   // Ss visible; all warps done reading Ks

        // prefetch tiles for kt+1 (overlaps exp + O-MMA)
        if (kt < qt) {
            const int k1 = (kt + 1) * 128;
            const unsigned int vdst = vs_s + (((kt + 1) & 1) * QBUF) * 4;
            #pragma unroll
            for (int u = 0; u < 4; u++) {
                int r = pr + u * 32;
                cp_async16(ks_s + (r * ATT_LDQ + pc4) * 4, &Kb[(size_t)(k1 + r) * DHD + pc4]);
                cp_async16(vdst + (r * ATT_LDQ + pc4) * 4, &Vb[(size_t)(k1 + r) * DHD + pc4]);
            }
            cp_commit();
        }

        // exp + causal mask + rowsum; e -> P and Ss
        {
            const int k0 = kt * 128;
            int r  = tid >> 2;
            int c0 = (tid & 3) * 32;
            int grow = m0 + r;
            float partial = 0.0f;
            #pragma unroll
            for (int c = 0; c < 32; c += 4) {
                int gc = k0 + c0 + c;
                float4 v = *(float4*)&Ss[r * ATT_LDS + c0 + c];
                v.x = (gc + 0 <= grow) ? __expf(v.x) : 0.0f;
                v.y = (gc + 1 <= grow) ? __expf(v.y) : 0.0f;
                v.z = (gc + 2 <= grow) ? __expf(v.z) : 0.0f;
                v.w = (gc + 3 <= grow) ? __expf(v.w) : 0.0f;
                partial += v.x + v.y + v.z + v.w;
                *(float4*)&Pb[(size_t)r * SS + gc] = v;
                *(float4*)&Ss[r * ATT_LDS + c0 + c] = v;
            }
            atomicAdd(&ls[r], partial);
        }
        __syncthreads();

        // O += e @ V  (warp tile 32x16)
        #pragma unroll
        for (int kk = 0; kk < 128; kk += 8) {
            wmma::fragment<wmma::matrix_a, 16, 16, 8, wmma::precision::tf32, wmma::row_major> a[2];
            wmma::fragment<wmma::matrix_b, 16, 16, 8, wmma::precision::tf32, wmma::row_major> b;
            #pragma unroll
            for (int i = 0; i < 2; i++)
                wmma::load_matrix_sync(a[i], &Ss[(wm * 32 + i * 16) * ATT_LDS + kk], ATT_LDS);
            wmma::load_matrix_sync(b, &Vs[cur + kk * ATT_LDQ + wn * 16], ATT_LDQ);
            #pragma unroll
            for (int i = 0; i < 2; i++)
                wmma::mma_sync(co[i], a[i], b, co[i]);
        }
        __syncthreads();
    }

    // zero-fill fully masked P region
    const int zc0 = (qt + 1) * 128;
    if (zc0 < SS) {
        const int rl4 = (SS - zc0) >> 2;
        const float4 z4 = make_float4(0.f, 0.f, 0.f, 0.f);
        for (int i = tid; i < 128 * rl4; i += 512) {
            int r = i / rl4, c4 = (i - r * rl4) * 4;
            *(float4*)&Pb[(size_t)r * SS + zc0 + c4] = z4;
        }
    }

    // stage O to smem, normalize, write AV
    #pragma unroll
    for (int i = 0; i < 2; i++)
        wmma::store_matrix_sync(&Ss[(wm * 32 + i * 16) * ATT_LDQ + wn * 16],
                                co[i], ATT_LDQ, wmma::mem_row_major);
    __syncthreads();

    const int bi = bh / HH, hi = bh % HH;
    {
        int r  = tid >> 2;
        int c0 = (tid & 3) * 16;
        float inv = 1.0f / ls[r];
        float* dst = AV + ((size_t)bi * SS + m0 + r) * DD + hi * DHD + c0;
        #pragma unroll
        for (int c = 0; c < 16; c += 4) {
            float4 v = *(float4*)&Ss[r * ATT_LDQ + c0 + c];
            v.x *= inv; v.y *= inv; v.z *= inv; v.w *= inv;
            *(float4*)&dst[c] = v;
        }
    }

    // rescale lower-triangle P by 1/rowsum
    {
        const int rl4 = zc0 >> 2;
        for (int i = tid; i < 128 * rl4; i += 512) {
            int r = i / rl4, c4 = (i - r * rl4) * 4;
            float inv = 1.0f / ls[r];
            float4 v = *(float4*)&Pb[(size_t)r * SS + c4];
            v.x *= inv; v.y *= inv; v.z *= inv; v.w *= inv;
            *(float4*)&Pb[(size_t)r * SS + c4] = v;
        }
    }
}

// ---------------- bias + exact GELU ----------------------------------------
__global__ void bias_gelu(float* __restrict__ F, const float* __restrict__ bias)
{
    const int idx4 = blockIdx.x * 256 + threadIdx.x;
    const size_t base = (size_t)idx4 * 4;
    float4 v = *(float4*)&F[base];
    const int col = (int)(base % DFF);
    float4 bb = *(const float4*)&bias[col];
    v.x += bb.x; v.y += bb.y; v.z += bb.z; v.w += bb.w;
    v.x = 0.5f * v.x * (1.0f + erff(v.x * 0.70710678118654752f));
    v.y = 0.5f * v.y * (1.0f + erff(v.y * 0.70710678118654752f));
    v.z = 0.5f * v.z * (1.0f + erff(v.z * 0.70710678118654752f));
    v.w = 0.5f * v.w * (1.0f + erff(v.w * 0.70710678118654752f));
    *(float4*)&F[base] = v;
}

// ---------------- fused residual add (+bias) + LayerNorm ------------------
__global__ void add_ln(const float* __restrict__ A, const float* __restrict__ Bv,
                       const float* __restrict__ bias,
                       const float* __restrict__ gamma, const float* __restrict__ beta,
                       float* __restrict__ out)
{
    const int row = blockIdx.x;
    const int tid = threadIdx.x;
    __shared__ float buf[DD];
    __shared__ float red[8];

    const float* a  = A  + (size_t)row * DD;
    const float* bp = Bv + (size_t)row * DD;

    float lsum = 0.f;
    #pragma unroll
    for (int i = 0; i < 3; i++) {
        int c = tid + i * 256;
        float v = a[c] + bp[c] + (bias ? bias[c] : 0.0f);
        buf[c] = v;
        lsum += v;
    }
    #pragma unroll
    for (int o = 16; o; o >>= 1) lsum += __shfl_xor_sync(0xffffffffu, lsum, o);
    if ((tid & 31) == 0) red[tid >> 5] = lsum;
    __syncthreads();
    float mu = (red[0]+red[1]+red[2]+red[3]+red[4]+red[5]+red[6]+red[7]) * (1.0f / DD);

    float lvar = 0.f;
    #pragma unroll
    for (int i = 0; i < 3; i++) {
        int c = tid + i * 256;
        float d = buf[c] - mu;
        lvar += d * d;
    }
    #pragma unroll
    for (int o = 16; o; o >>= 1) lvar += __shfl_xor_sync(0xffffffffu, lvar, o);
    __syncthreads();
    if ((tid & 31) == 0) red[tid >> 5] = lvar;
    __syncthreads();
    float var = (red[0]+red[1]+red[2]+red[3]+red[4]+red[5]+red[6]+red[7]) * (1.0f / DD);
    float inv = rsqrtf(var + 1e-5f);

    float* o = out + (size_t)row * DD;
    #pragma unroll
    for (int i = 0; i < 3; i++) {
        int c = tid + i * 256;
        o[c] = (buf[c] - mu) * inv * gamma[c] + beta[c];
    }
}

// ---------------------------------------------------------------------------
extern "C" void kernel_launch(void* const* d_in, const int* in_sizes, int n_in,
                              void* d_out, int out_size)
{
    const float* x   = (const float*)d_in[0];
    const float* Wq  = (const float*)d_in[2];
    const float* Wk  = (const float*)d_in[3];
    const float* Wv  = (const float*)d_in[4];
    const float* Wo  = (const float*)d_in[5];
    const float* bo  = (const float*)d_in[6];
    const float* g1  = (const float*)d_in[7];
    const float* b1  = (const float*)d_in[8];
    const float* W1  = (const float*)d_in[9];
    const float* bb1 = (const float*)d_in[10];
    const float* W2  = (const float*)d_in[11];
    const float* bb2 = (const float*)d_in[12];
    const float* g2  = (const float*)d_in[13];
    const float* b2  = (const float*)d_in[14];

    float* y = (float*)d_out;
    float* P = y + Y_ELEMS;

    float *qp, *kp, *vp, *avp, *aop, *hp, *f1p, *f2p;
    cudaGetSymbolAddress((void**)&qp,  g_q);
    cudaGetSymbolAddress((void**)&kp,  g_k);
    cudaGetSymbolAddress((void**)&vp,  g_v);
    cudaGetSymbolAddress((void**)&avp, g_av);
    cudaGetSymbolAddress((void**)&aop, g_ao);
    cudaGetSymbolAddress((void**)&hp,  g_h);
    cudaGetSymbolAddress((void**)&f1p, g_f1);
    cudaGetSymbolAddress((void**)&f2p, g_f2);

    cudaFuncSetAttribute(gemm_tc_nt, cudaFuncAttributeMaxDynamicSharedMemorySize,
                         GEMM_SMEM_BYTES);
    cudaFuncSetAttribute(qkv_gemm, cudaFuncAttributeMaxDynamicSharedMemorySize,
                         GEMM_SMEM_BYTES);
    static const size_t att_smem = (size_t)ATT_SMEM_FLOATS * sizeof(float);
    cudaFuncSetAttribute(attn_fused, cudaFuncAttributeMaxDynamicSharedMemorySize,
                         (int)att_smem);

    dim3 g768 (DD  / 128, MM / 128);
    dim3 g3072(DFF / 128, MM / 128);
    dim3 gqkv (DD  / 128, MM / 128, 3);

    // QKV projections: single merged launch, head-split outputs
    qkv_gemm<<<gqkv, 256, GEMM_SMEM_BYTES>>>(x, Wq, Wk, Wv, qp, kp, vp);

    // fused attention (cp.async pipelined)
    attn_fused<<<dim3(SS / 128, BB * HH), 512, att_smem>>>(qp, kp, vp, P, avp);

    // output projection (bias folded into add_ln)
    gemm_tc_nt<<<g768, 256, GEMM_SMEM_BYTES>>>(avp, Wo, aop, DD, DD);

    add_ln<<<MM, 256>>>(x, aop, bo, g1, b1, hp);

    gemm_tc_nt<<<g3072, 256, GEMM_SMEM_BYTES>>>(hp, W1, f1p, DFF, DD);
    bias_gelu<<<(int)((size_t)MM * DFF / 4 / 256), 256>>>(f1p, bb1);
    gemm_tc_nt<<<g768, 256, GEMM_SMEM_BYTES>>>(f1p, W2, f2p, DD, DFF);

    add_ln<<<MM, 256>>>(hp, f2p, bb2, g2, b2, y);
}

// round 10
// speedup vs baseline: 1.3640x; 1.3640x over previous
#include <cuda_runtime.h>
#include <cstdint>
#include <math.h>
#include <mma.h>

using namespace nvcuda;

// Problem constants
#define BB 2
#define SS 2048
#define HH 12
#define DHD 64
#define DD 768
#define DFF 3072
#define MM (BB*SS)
#define Y_ELEMS ((size_t)BB*SS*DD)

// ---------------- scratch (device globals) ---------------------------------
__device__ float g_q [BB*HH*SS*DHD];
__device__ float g_k [BB*HH*SS*DHD];
__device__ float g_v [BB*HH*SS*DHD];
__device__ float g_av[BB*SS*DD];
__device__ float g_ao[BB*SS*DD];
__device__ float g_h [BB*SS*DD];
__device__ float g_f1[BB*SS*DFF];
__device__ float g_f2[BB*SS*DD];

__device__ __forceinline__ void cp_async16(unsigned int dst, const void* src) {
    asm volatile("cp.async.cg.shared.global [%0], [%1], 16;\n" :: "r"(dst), "l"(src));
}
__device__ __forceinline__ void cp_commit() {
    asm volatile("cp.async.commit_group;\n");
}
__device__ __forceinline__ void cp_wait0() {
    asm volatile("cp.async.wait_group 0;\n");
}
__device__ __forceinline__ void cp_wait1() {
    asm volatile("cp.async.wait_group 1;\n");
}

// ========  tf32 NT GEMM, 3-stage cp.async, 512 threads (16 warps)  =========
// Raw fp32 in smem; tf32 HMMA truncates mantissa in hardware.
#define GLD 36
#define GBUF (128*GLD)
#define GSTG 3
#define GEMM_SMEM_BYTES (GSTG*2*GBUF*4)   // 110,592 B

// C[m,n] = sum_k A[m,k]*B[n,k].  128x128 CTA tile, warp tile 32x32.
template<int MODE>
__device__ __forceinline__ void gemm_body(const float* __restrict__ A,
                                          const float* __restrict__ B,
                                          float* __restrict__ C,
                                          int N, int K, int m0, int n0)
{
    extern __shared__ float gsm[];
    float* As = gsm;                    // [GSTG][128][36]
    float* Bs = gsm + GSTG*GBUF;        // [GSTG][128][36]

    const int tid  = threadIdx.x;       // 512
    const int warp = tid >> 5;          // 0..15
    const int wm   = warp & 3;          // 4 warps in m (32 rows each)
    const int wn   = warp >> 2;         // 4 warps in n (32 cols each)
    const int lr   = tid >> 3;          // 0..63
    const int lc4  = (tid & 7) * 4;     // 0..28

    const unsigned int as_s = (unsigned int)__cvta_generic_to_shared(As);
    const unsigned int bs_s = (unsigned int)__cvta_generic_to_shared(Bs);

    wmma::fragment<wmma::accumulator, 16, 16, 8, float> c[2][2];
    #pragma unroll
    for (int i = 0; i < 2; i++)
        #pragma unroll
        for (int j = 0; j < 2; j++)
            wmma::fill_fragment(c[i][j], 0.0f);

    const int T = K >> 5;

    // issue copy for k-tile t into stage t%GSTG
    auto issue = [&](int t) {
        const int k0 = t << 5;
        const unsigned int soff = (unsigned int)((t % GSTG) * GBUF * 4);
        #pragma unroll
        for (int i = 0; i < 2; i++) {
            int row = lr + i * 64;
            cp_async16(as_s + soff + (unsigned int)((row * GLD + lc4) * 4),
                       &A[(size_t)(m0 + row) * K + k0 + lc4]);
            cp_async16(bs_s + soff + (unsigned int)((row * GLD + lc4) * 4),
                       &B[(size_t)(n0 + row) * K + k0 + lc4]);
        }
        cp_commit();
    };

    issue(0);
    if (T > 1) issue(1);

    for (int t = 0; t < T; t++) {
        if (t + 1 < T) cp_wait1(); else cp_wait0();
        __syncthreads();
        if (t + 2 < T) issue(t + 2);

        const int cur = (t % GSTG) * GBUF;
        #pragma unroll
        for (int kk = 0; kk < 32; kk += 8) {
            wmma::fragment<wmma::matrix_a, 16, 16, 8, wmma::precision::tf32, wmma::row_major> a[2];
            wmma::fragment<wmma::matrix_b, 16, 16, 8, wmma::precision::tf32, wmma::col_major> b[2];
            #pragma unroll
            for (int i = 0; i < 2; i++)
                wmma::load_matrix_sync(a[i], &As[cur + (wm * 32 + i * 16) * GLD + kk], GLD);
            #pragma unroll
            for (int j = 0; j < 2; j++)
                wmma::load_matrix_sync(b[j], &Bs[cur + (wn * 32 + j * 16) * GLD + kk], GLD);
            #pragma unroll
            for (int i = 0; i < 2; i++)
                #pragma unroll
                for (int j = 0; j < 2; j++)
                    wmma::mma_sync(c[i][j], a[i], b[j], c[i][j]);
        }
        __syncthreads();
    }

    #pragma unroll
    for (int i = 0; i < 2; i++) {
        int m = m0 + wm * 32 + i * 16;
        #pragma unroll
        for (int j = 0; j < 2; j++) {
            int n = n0 + wn * 32 + j * 16;
            if (MODE == 3) {
                int bidx = m >> 11, s = m & 2047;
                int h = n >> 6, dh = n & 63;
                float* dst = C + (((size_t)(bidx * HH + h)) * SS + s) * DHD + dh;
                wmma::store_matrix_sync(dst, c[i][j], DHD, wmma::mem_row_major);
            } else {
                wmma::store_matrix_sync(C + (size_t)m * N + n, c[i][j], N, wmma::mem_row_major);
            }
        }
    }
}

__global__ void __launch_bounds__(512)
gemm_tc_nt(const float* __restrict__ A, const float* __restrict__ B,
           float* __restrict__ C, int N, int K)
{
    gemm_body<0>(A, B, C, N, K, blockIdx.y * 128, blockIdx.x * 128);
}

// merged QKV: grid.z selects (W, out) pair; head-split store
__global__ void __launch_bounds__(512)
qkv_gemm(const float* __restrict__ X,
         const float* __restrict__ Wq, const float* __restrict__ Wk,
         const float* __restrict__ Wv,
         float* __restrict__ Qo, float* __restrict__ Ko, float* __restrict__ Vo)
{
    const float* B = (blockIdx.z == 0) ? Wq : (blockIdx.z == 1) ? Wk : Wv;
    float*       C = (blockIdx.z == 0) ? Qo : (blockIdx.z == 1) ? Ko : Vo;
    gemm_body<3>(X, B, C, DD, DD, blockIdx.y * 128, blockIdx.x * 128);
}

// ==============  fused flash attention, cp.async pipelined  ================
#define ATT_LDQ 68
#define QBUF (128*ATT_LDQ)
#define ATT_LDS 132
#define ATT_SMEM_FLOATS (4*QBUF + 128*ATT_LDS + 128)   // Q,K,V[2],S,ls

__global__ void __launch_bounds__(512, 1)
attn_fused(const float* __restrict__ Q, const float* __restrict__ K,
           const float* __restrict__ V, float* __restrict__ P,
           float* __restrict__ AV)
{
    extern __shared__ float sm[];
    float* Qs = sm;                 // [128][68]
    float* Ks = Qs + QBUF;          // [128][68]
    float* Vs = Ks + QBUF;          // [2][128][68]
    float* Ss = Vs + 2*QBUF;        // [128][132]
    float* ls = Ss + 128 * ATT_LDS; // [128]

    const int bh  = blockIdx.y;
    const int qt  = gridDim.x - 1 - blockIdx.x;
    const int m0  = qt * 128;
    const int tid = threadIdx.x;
    const int warp = tid >> 5;
    const int wm = warp & 3;
    const int wn = warp >> 2;

    const float* Qb = Q + ((size_t)bh * SS + m0) * DHD;
    const float* Kb = K + (size_t)bh * SS * DHD;
    const float* Vb = V + (size_t)bh * SS * DHD;
    float* Pb = P + ((size_t)bh * SS + m0) * SS;

    const int pr  = tid >> 4;
    const int pc4 = (tid & 15) * 4;
    const unsigned int ks_s = (unsigned int)__cvta_generic_to_shared(Ks);
    const unsigned int vs_s = (unsigned int)__cvta_generic_to_shared(Vs);

    // load Q tile, pre-scaled by 1/8
    for (int i = tid; i < 128 * 16; i += 512) {
        int r = i >> 4, c4 = (i & 15) * 4;
        float4 v = *(const float4*)&Qb[(size_t)r * DHD + c4];
        v.x *= 0.125f; v.y *= 0.125f; v.z *= 0.125f; v.w *= 0.125f;
        *(float4*)&Qs[r * ATT_LDQ + c4] = v;
    }
    if (tid < 128) ls[tid] = 0.0f;

    // issue copies for kt = 0
    #pragma unroll
    for (int u = 0; u < 4; u++) {
        int r = pr + u * 32;
        cp_async16(ks_s + (r * ATT_LDQ + pc4) * 4, &Kb[(size_t)r * DHD + pc4]);
        cp_async16(vs_s + (r * ATT_LDQ + pc4) * 4, &Vb[(size_t)r * DHD + pc4]);
    }
    cp_commit();

    wmma::fragment<wmma::accumulator, 16, 16, 8, float> co[2];
    #pragma unroll
    for (int i = 0; i < 2; i++) wmma::fill_fragment(co[i], 0.0f);

    for (int kt = 0; kt <= qt; kt++) {
        const int cur = (kt & 1) * QBUF;
        cp_wait0();
        __syncthreads();

        // S = Qs @ Ks^T  (warp tile 32x32)
        wmma::fragment<wmma::accumulator, 16, 16, 8, float> cs[2][2];
        #pragma unroll
        for (int i = 0; i < 2; i++)
            #pragma unroll
            for (int j = 0; j < 2; j++)
                wmma::fill_fragment(cs[i][j], 0.0f);

        #pragma unroll
        for (int kk = 0; kk < 64; kk += 8) {
            wmma::fragment<wmma::matrix_a, 16, 16, 8, wmma::precision::tf32, wmma::row_major> a[2];
            wmma::fragment<wmma::matrix_b, 16, 16, 8, wmma::precision::tf32, wmma::col_major> b[2];
            #pragma unroll
            for (int i = 0; i < 2; i++)
                wmma::load_matrix_sync(a[i], &Qs[(wm * 32 + i * 16) * ATT_LDQ + kk], ATT_LDQ);
            #pragma unroll
            for (int j = 0; j < 2; j++)
                wmma::load_matrix_sync(b[j], &Ks[(wn * 32 + j * 16) * ATT_LDQ + kk], ATT_LDQ);
            #pragma unroll
            for (int i = 0; i < 2; i++)
                #pragma unroll
                for (int j = 0; j < 2; j++)
                    wmma::mma_sync(cs[i][j], a[i], b[j], cs[i][j]);
        }
        #pragma unroll
        for (int i = 0; i < 2; i++)
            #pragma unroll
            for (int j = 0; j < 2; j++)
                wmma::store_matrix_sync(&Ss[(wm * 32 + i * 16) * ATT_LDS + wn * 32 + j * 16],
                                        cs[i][j], ATT_LDS, wmma::mem_row_major);
        __syncthreads();   // Ss visible; all warps done reading Ks

        // prefetch tiles for kt+1 (overlaps exp + O-MMA)
        if (kt < qt) {
            const int k1 = (kt + 1) * 128;
            const unsigned int vdst = vs_s + (((kt + 1) & 1) * QBUF) * 4;
            #pragma unroll
            for (int u = 0; u < 4; u++) {
                int r = pr + u * 32;
                cp_async16(ks_s + (r * ATT_LDQ + pc4) * 4, &Kb[(size_t)(k1 + r) * DHD + pc4]);
                cp_async16(vdst + (r * ATT_LDQ + pc4) * 4, &Vb[(size_t)(k1 + r) * DHD + pc4]);
            }
            cp_commit();
        }

        // exp + causal mask + rowsum; e -> P and Ss
        {
            const int k0 = kt * 128;
            int r  = tid >> 2;
            int c0 = (tid & 3) * 32;
            int grow = m0 + r;
            float partial = 0.0f;
            #pragma unroll
            for (int c = 0; c < 32; c += 4) {
                int gc = k0 + c0 + c;
                float4 v = *(float4*)&Ss[r * ATT_LDS + c0 + c];
                v.x = (gc + 0 <= grow) ? __expf(v.x) : 0.0f;
                v.y = (gc + 1 <= grow) ? __expf(v.y) : 0.0f;
                v.z = (gc + 2 <= grow) ? __expf(v.z) : 0.0f;
                v.w = (gc + 3 <= grow) ? __expf(v.w) : 0.0f;
                partial += v.x + v.y + v.z + v.w;
                *(float4*)&Pb[(size_t)r * SS + gc] = v;
                *(float4*)&Ss[r * ATT_LDS + c0 + c] = v;
            }
            atomicAdd(&ls[r], partial);
        }
        __syncthreads();

        // O += e @ V  (warp tile 32x16)
        #pragma unroll
        for (int kk = 0; kk < 128; kk += 8) {
            wmma::fragment<wmma::matrix_a, 16, 16, 8, wmma::precision::tf32, wmma::row_major> a[2];
            wmma::fragment<wmma::matrix_b, 16, 16, 8, wmma::precision::tf32, wmma::row_major> b;
            #pragma unroll
            for (int i = 0; i < 2; i++)
                wmma::load_matrix_sync(a[i], &Ss[(wm * 32 + i * 16) * ATT_LDS + kk], ATT_LDS);
            wmma::load_matrix_sync(b, &Vs[cur + kk * ATT_LDQ + wn * 16], ATT_LDQ);
            #pragma unroll
            for (int i = 0; i < 2; i++)
                wmma::mma_sync(co[i], a[i], b, co[i]);
        }
        __syncthreads();
    }

    // zero-fill fully masked P region
    const int zc0 = (qt + 1) * 128;
    if (zc0 < SS) {
        const int rl4 = (SS - zc0) >> 2;
        const float4 z4 = make_float4(0.f, 0.f, 0.f, 0.f);
        for (int i = tid; i < 128 * rl4; i += 512) {
            int r = i / rl4, c4 = (i - r * rl4) * 4;
            *(float4*)&Pb[(size_t)r * SS + zc0 + c4] = z4;
        }
    }

    // stage O to smem, normalize, write AV
    #pragma unroll
    for (int i = 0; i < 2; i++)
        wmma::store_matrix_sync(&Ss[(wm * 32 + i * 16) * ATT_LDQ + wn * 16],
                                co[i], ATT_LDQ, wmma::mem_row_major);
    __syncthreads();

    const int bi = bh / HH, hi = bh % HH;
    {
        int r  = tid >> 2;
        int c0 = (tid & 3) * 16;
        float inv = 1.0f / ls[r];
        float* dst = AV + ((size_t)bi * SS + m0 + r) * DD + hi * DHD + c0;
        #pragma unroll
        for (int c = 0; c < 16; c += 4) {
            float4 v = *(float4*)&Ss[r * ATT_LDQ + c0 + c];
            v.x *= inv; v.y *= inv; v.z *= inv; v.w *= inv;
            *(float4*)&dst[c] = v;
        }
    }

    // rescale lower-triangle P by 1/rowsum
    {
        const int rl4 = zc0 >> 2;
        for (int i = tid; i < 128 * rl4; i += 512) {
            int r = i / rl4, c4 = (i - r * rl4) * 4;
            float inv = 1.0f / ls[r];
            float4 v = *(float4*)&Pb[(size_t)r * SS + c4];
            v.x *= inv; v.y *= inv; v.z *= inv; v.w *= inv;
            *(float4*)&Pb[(size_t)r * SS + c4] = v;
        }
    }
}

// ---------------- bias + exact GELU ----------------------------------------
__global__ void bias_gelu(float* __restrict__ F, const float* __restrict__ bias)
{
    const int idx4 = blockIdx.x * 256 + threadIdx.x;
    const size_t base = (size_t)idx4 * 4;
    float4 v = *(float4*)&F[base];
    const int col = (int)(base % DFF);
    float4 bb = *(const float4*)&bias[col];
    v.x += bb.x; v.y += bb.y; v.z += bb.z; v.w += bb.w;
    v.x = 0.5f * v.x * (1.0f + erff(v.x * 0.70710678118654752f));
    v.y = 0.5f * v.y * (1.0f + erff(v.y * 0.70710678118654752f));
    v.z = 0.5f * v.z * (1.0f + erff(v.z * 0.70710678118654752f));
    v.w = 0.5f * v.w * (1.0f + erff(v.w * 0.70710678118654752f));
    *(float4*)&F[base] = v;
}

// ---------------- fused residual add (+bias) + LayerNorm ------------------
__global__ void add_ln(const float* __restrict__ A, const float* __restrict__ Bv,
                       const float* __restrict__ bias,
                       const float* __restrict__ gamma, const float* __restrict__ beta,
                       float* __restrict__ out)
{
    const int row = blockIdx.x;
    const int tid = threadIdx.x;
    __shared__ float buf[DD];
    __shared__ float red[8];

    const float* a  = A  + (size_t)row * DD;
    const float* bp = Bv + (size_t)row * DD;

    float lsum = 0.f;
    #pragma unroll
    for (int i = 0; i < 3; i++) {
        int c = tid + i * 256;
        float v = a[c] + bp[c] + (bias ? bias[c] : 0.0f);
        buf[c] = v;
        lsum += v;
    }
    #pragma unroll
    for (int o = 16; o; o >>= 1) lsum += __shfl_xor_sync(0xffffffffu, lsum, o);
    if ((tid & 31) == 0) red[tid >> 5] = lsum;
    __syncthreads();
    float mu = (red[0]+red[1]+red[2]+red[3]+red[4]+red[5]+red[6]+red[7]) * (1.0f / DD);

    float lvar = 0.f;
    #pragma unroll
    for (int i = 0; i < 3; i++) {
        int c = tid + i * 256;
        float d = buf[c] - mu;
        lvar += d * d;
    }
    #pragma unroll
    for (int o = 16; o; o >>= 1) lvar += __shfl_xor_sync(0xffffffffu, lvar, o);
    __syncthreads();
    if ((tid & 31) == 0) red[tid >> 5] = lvar;
    __syncthreads();
    float var = (red[0]+red[1]+red[2]+red[3]+red[4]+red[5]+red[6]+red[7]) * (1.0f / DD);
    float inv = rsqrtf(var + 1e-5f);

    float* o = out + (size_t)row * DD;
    #pragma unroll
    for (int i = 0; i < 3; i++) {
        int c = tid + i * 256;
        o[c] = (buf[c] - mu) * inv * gamma[c] + beta[c];
    }
}

// ---------------------------------------------------------------------------
extern "C" void kernel_launch(void* const* d_in, const int* in_sizes, int n_in,
                              void* d_out, int out_size)
{
    const float* x   = (const float*)d_in[0];
    const float* Wq  = (const float*)d_in[2];
    const float* Wk  = (const float*)d_in[3];
    const float* Wv  = (const float*)d_in[4];
    const float* Wo  = (const float*)d_in[5];
    const float* bo  = (const float*)d_in[6];
    const float* g1  = (const float*)d_in[7];
    const float* b1  = (const float*)d_in[8];
    const float* W1  = (const float*)d_in[9];
    const float* bb1 = (const float*)d_in[10];
    const float* W2  = (const float*)d_in[11];
    const float* bb2 = (const float*)d_in[12];
    const float* g2  = (const float*)d_in[13];
    const float* b2  = (const float*)d_in[14];

    float* y = (float*)d_out;
    float* P = y + Y_ELEMS;

    float *qp, *kp, *vp, *avp, *aop, *hp, *f1p, *f2p;
    cudaGetSymbolAddress((void**)&qp,  g_q);
    cudaGetSymbolAddress((void**)&kp,  g_k);
    cudaGetSymbolAddress((void**)&vp,  g_v);
    cudaGetSymbolAddress((void**)&avp, g_av);
    cudaGetSymbolAddress((void**)&aop, g_ao);
    cudaGetSymbolAddress((void**)&hp,  g_h);
    cudaGetSymbolAddress((void**)&f1p, g_f1);
    cudaGetSymbolAddress((void**)&f2p, g_f2);

    cudaFuncSetAttribute(gemm_tc_nt, cudaFuncAttributeMaxDynamicSharedMemorySize,
                         GEMM_SMEM_BYTES);
    cudaFuncSetAttribute(qkv_gemm, cudaFuncAttributeMaxDynamicSharedMemorySize,
                         GEMM_SMEM_BYTES);
    static const size_t att_smem = (size_t)ATT_SMEM_FLOATS * sizeof(float);
    cudaFuncSetAttribute(attn_fused, cudaFuncAttributeMaxDynamicSharedMemorySize,
                         (int)att_smem);

    dim3 g768 (DD  / 128, MM / 128);
    dim3 g3072(DFF / 128, MM / 128);
    dim3 gqkv (DD  / 128, MM / 128, 3);

    // QKV projections: single merged launch, head-split outputs
    qkv_gemm<<<gqkv, 512, GEMM_SMEM_BYTES>>>(x, Wq, Wk, Wv, qp, kp, vp);

    // fused attention (cp.async pipelined)
    attn_fused<<<dim3(SS / 128, BB * HH), 512, att_smem>>>(qp, kp, vp, P, avp);

    // output projection (bias folded into add_ln)
    gemm_tc_nt<<<g768, 512, GEMM_SMEM_BYTES>>>(avp, Wo, aop, DD, DD);

    add_ln<<<MM, 256>>>(x, aop, bo, g1, b1, hp);

    gemm_tc_nt<<<g3072, 512, GEMM_SMEM_BYTES>>>(hp, W1, f1p, DFF, DD);
    bias_gelu<<<(int)((size_t)MM * DFF / 4 / 256), 256>>>(f1p, bb1);
    gemm_tc_nt<<<g768, 512, GEMM_SMEM_BYTES>>>(f1p, W2, f2p, DD, DFF);

    add_ln<<<MM, 256>>>(hp, f2p, bb2, g2, b2, y);
}

// round 11
// speedup vs baseline: 1.4371x; 1.0535x over previous
#include <cuda_runtime.h>
#include <cstdint>
#include <math.h>
#include <mma.h>

using namespace nvcuda;

// Problem constants
#define BB 2
#define SS 2048
#define HH 12
#define DHD 64
#define DD 768
#define DFF 3072
#define MM (BB*SS)
#define Y_ELEMS ((size_t)BB*SS*DD)

// ---------------- scratch (device globals) ---------------------------------
__device__ float g_q [BB*HH*SS*DHD];
__device__ float g_k [BB*HH*SS*DHD];
__device__ float g_v [BB*HH*SS*DHD];
__device__ float g_av[BB*SS*DD];
__device__ float g_ao[BB*SS*DD];
__device__ float g_h [BB*SS*DD];
__device__ float g_f1[BB*SS*DFF];
__device__ float g_f2[BB*SS*DD];

__device__ __forceinline__ void cp_async16(unsigned int dst, const void* src) {
    asm volatile("cp.async.cg.shared.global [%0], [%1], 16;\n" :: "r"(dst), "l"(src));
}
__device__ __forceinline__ void cp_commit() {
    asm volatile("cp.async.commit_group;\n");
}
__device__ __forceinline__ void cp_wait0() {
    asm volatile("cp.async.wait_group 0;\n");
}
__device__ __forceinline__ void cp_wait1() {
    asm volatile("cp.async.wait_group 1;\n");
}

// FMA-pipe exp: range-reduce, degree-5 2^f poly, exponent splice.
// rel err ~2e-7 on the score range; ~20x MUFU.EX2 throughput.
__device__ __forceinline__ float fexp(float x) {
    float t  = fmaxf(x, -80.0f) * 1.4426950408889634f;
    float fi = rintf(t);
    float f  = t - fi;
    float p  = 1.3393036e-3f;
    p = fmaf(p, f, 9.6181316e-3f);
    p = fmaf(p, f, 5.5504109e-2f);
    p = fmaf(p, f, 2.4022651e-1f);
    p = fmaf(p, f, 6.9314718e-1f);
    p = fmaf(p, f, 1.0f);
    int ei = (int)fi;
    return __int_as_float(__float_as_int(p) + (ei << 23));
}

// ============  tf32 NT GEMM, 3-stage cp.async pipeline  ====================
// Raw fp32 in smem; tf32 HMMA truncates mantissa in hardware.
#define GLD 36
#define GBUF (128*GLD)
#define GSTG 3
#define GEMM_SMEM_BYTES (GSTG*2*GBUF*4)   // 110,592 B

// C[m,n] = sum_k A[m,k]*B[n,k]
template<int MODE>
__device__ __forceinline__ void gemm_body(const float* __restrict__ A,
                                          const float* __restrict__ B,
                                          float* __restrict__ C,
                                          int N, int K, int m0, int n0)
{
    extern __shared__ float gsm[];
    float* As = gsm;                    // [GSTG][128][36]
    float* Bs = gsm + GSTG*GBUF;        // [GSTG][128][36]

    const int tid  = threadIdx.x;
    const int warp = tid >> 5;
    const int wm   = warp & 1;
    const int wn   = warp >> 1;
    const int lr   = tid >> 3;          // 0..31
    const int lc4  = (tid & 7) * 4;     // 0..28

    const unsigned int as_s = (unsigned int)__cvta_generic_to_shared(As);
    const unsigned int bs_s = (unsigned int)__cvta_generic_to_shared(Bs);

    wmma::fragment<wmma::accumulator, 16, 16, 8, float> c[4][2];
    #pragma unroll
    for (int i = 0; i < 4; i++)
        #pragma unroll
        for (int j = 0; j < 2; j++)
            wmma::fill_fragment(c[i][j], 0.0f);

    const int T = K >> 5;

    auto issue = [&](int t) {
        const int k0 = t << 5;
        const unsigned int soff = (unsigned int)((t % GSTG) * GBUF * 4);
        #pragma unroll
        for (int i = 0; i < 4; i++) {
            int row = lr + i * 32;
            cp_async16(as_s + soff + (unsigned int)((row * GLD + lc4) * 4),
                       &A[(size_t)(m0 + row) * K + k0 + lc4]);
            cp_async16(bs_s + soff + (unsigned int)((row * GLD + lc4) * 4),
                       &B[(size_t)(n0 + row) * K + k0 + lc4]);
        }
        cp_commit();
    };

    issue(0);
    if (T > 1) issue(1);

    for (int t = 0; t < T; t++) {
        if (t + 1 < T) cp_wait1(); else cp_wait0();
        __syncthreads();
        if (t + 2 < T) issue(t + 2);

        const int cur = (t % GSTG) * GBUF;
        #pragma unroll
        for (int kk = 0; kk < 32; kk += 8) {
            wmma::fragment<wmma::matrix_a, 16, 16, 8, wmma::precision::tf32, wmma::row_major> a[4];
            wmma::fragment<wmma::matrix_b, 16, 16, 8, wmma::precision::tf32, wmma::col_major> b[2];
            #pragma unroll
            for (int i = 0; i < 4; i++)
                wmma::load_matrix_sync(a[i], &As[cur + (wm * 64 + i * 16) * GLD + kk], GLD);
            #pragma unroll
            for (int j = 0; j < 2; j++)
                wmma::load_matrix_sync(b[j], &Bs[cur + (wn * 32 + j * 16) * GLD + kk], GLD);
            #pragma unroll
            for (int i = 0; i < 4; i++)
                #pragma unroll
                for (int j = 0; j < 2; j++)
                    wmma::mma_sync(c[i][j], a[i], b[j], c[i][j]);
        }
        __syncthreads();
    }

    #pragma unroll
    for (int i = 0; i < 4; i++) {
        int m = m0 + wm * 64 + i * 16;
        #pragma unroll
        for (int j = 0; j < 2; j++) {
            int n = n0 + wn * 32 + j * 16;
            if (MODE == 3) {
                int bidx = m >> 11, s = m & 2047;
                int h = n >> 6, dh = n & 63;
                float* dst = C + (((size_t)(bidx * HH + h)) * SS + s) * DHD + dh;
                wmma::store_matrix_sync(dst, c[i][j], DHD, wmma::mem_row_major);
            } else {
                wmma::store_matrix_sync(C + (size_t)m * N + n, c[i][j], N, wmma::mem_row_major);
            }
        }
    }
}

__global__ void __launch_bounds__(256)
gemm_tc_nt(const float* __restrict__ A, const float* __restrict__ B,
           float* __restrict__ C, int N, int K)
{
    gemm_body<0>(A, B, C, N, K, blockIdx.y * 128, blockIdx.x * 128);
}

// merged QKV: grid.z selects (W, out) pair; head-split store
__global__ void __launch_bounds__(256)
qkv_gemm(const float* __restrict__ X,
         const float* __restrict__ Wq, const float* __restrict__ Wk,
         const float* __restrict__ Wv,
         float* __restrict__ Qo, float* __restrict__ Ko, float* __restrict__ Vo)
{
    const float* B = (blockIdx.z == 0) ? Wq : (blockIdx.z == 1) ? Wk : Wv;
    float*       C = (blockIdx.z == 0) ? Qo : (blockIdx.z == 1) ? Ko : Vo;
    gemm_body<3>(X, B, C, DD, DD, blockIdx.y * 128, blockIdx.x * 128);
}

// ==============  fused flash attention, cp.async pipelined  ================
#define ATT_LDQ 68
#define QBUF (128*ATT_LDQ)
#define ATT_LDS 132
#define ATT_SMEM_FLOATS (4*QBUF + 128*ATT_LDS + 128)   // Q,K,V[2],S,ls

__global__ void __launch_bounds__(512, 1)
attn_fused(const float* __restrict__ Q, const float* __restrict__ K,
           const float* __restrict__ V, float* __restrict__ P,
           float* __restrict__ AV)
{
    extern __shared__ float sm[];
    float* Qs = sm;                 // [128][68]
    float* Ks = Qs + QBUF;          // [128][68]
    float* Vs = Ks + QBUF;          // [2][128][68]
    float* Ss = Vs + 2*QBUF;        // [128][132]
    float* ls = Ss + 128 * ATT_LDS; // [128]

    const int bh  = blockIdx.y;
    const int qt  = gridDim.x - 1 - blockIdx.x;
    const int m0  = qt * 128;
    const int tid = threadIdx.x;
    const int warp = tid >> 5;
    const int wm = warp & 3;
    const int wn = warp >> 2;

    const float* Qb = Q + ((size_t)bh * SS + m0) * DHD;
    const float* Kb = K + (size_t)bh * SS * DHD;
    const float* Vb = V + (size_t)bh * SS * DHD;
    float* Pb = P + ((size_t)bh * SS + m0) * SS;

    const int pr  = tid >> 4;
    const int pc4 = (tid & 15) * 4;
    const unsigned int ks_s = (unsigned int)__cvta_generic_to_shared(Ks);
    const unsigned int vs_s = (unsigned int)__cvta_generic_to_shared(Vs);

    // load Q tile, pre-scaled by 1/8
    for (int i = tid; i < 128 * 16; i += 512) {
        int r = i >> 4, c4 = (i & 15) * 4;
        float4 v = *(const float4*)&Qb[(size_t)r * DHD + c4];
        v.x *= 0.125f; v.y *= 0.125f; v.z *= 0.125f; v.w *= 0.125f;
        *(float4*)&Qs[r * ATT_LDQ + c4] = v;
    }
    if (tid < 128) ls[tid] = 0.0f;

    // issue copies for kt = 0
    #pragma unroll
    for (int u = 0; u < 4; u++) {
        int r = pr + u * 32;
        cp_async16(ks_s + (r * ATT_LDQ + pc4) * 4, &Kb[(size_t)r * DHD + pc4]);
        cp_async16(vs_s + (r * ATT_LDQ + pc4) * 4, &Vb[(size_t)r * DHD + pc4]);
    }
    cp_commit();

    wmma::fragment<wmma::accumulator, 16, 16, 8, float> co[2];
    #pragma unroll
    for (int i = 0; i < 2; i++) wmma::fill_fragment(co[i], 0.0f);

    for (int kt = 0; kt <= qt; kt++) {
        const int cur = (kt & 1) * QBUF;
        cp_wait0();
        __syncthreads();

        // S = Qs @ Ks^T  (warp tile 32x32)
        wmma::fragment<wmma::accumulator, 16, 16, 8, float> cs[2][2];
        #pragma unroll
        for (int i = 0; i < 2; i++)
            #pragma unroll
            for (int j = 0; j < 2; j++)
                wmma::fill_fragment(cs[i][j], 0.0f);

        #pragma unroll
        for (int kk = 0; kk < 64; kk += 8) {
            wmma::fragment<wmma::matrix_a, 16, 16, 8, wmma::precision::tf32, wmma::row_major> a[2];
            wmma::fragment<wmma::matrix_b, 16, 16, 8, wmma::precision::tf32, wmma::col_major> b[2];
            #pragma unroll
            for (int i = 0; i < 2; i++)
                wmma::load_matrix_sync(a[i], &Qs[(wm * 32 + i * 16) * ATT_LDQ + kk], ATT_LDQ);
            #pragma unroll
            for (int j = 0; j < 2; j++)
                wmma::load_matrix_sync(b[j], &Ks[(wn * 32 + j * 16) * ATT_LDQ + kk], ATT_LDQ);
            #pragma unroll
            for (int i = 0; i < 2; i++)
                #pragma unroll
                for (int j = 0; j < 2; j++)
                    wmma::mma_sync(cs[i][j], a[i], b[j], cs[i][j]);
        }
        #pragma unroll
        for (int i = 0; i < 2; i++)
            #pragma unroll
            for (int j = 0; j < 2; j++)
                wmma::store_matrix_sync(&Ss[(wm * 32 + i * 16) * ATT_LDS + wn * 32 + j * 16],
                                        cs[i][j], ATT_LDS, wmma::mem_row_major);
        __syncthreads();   // Ss visible; all warps done reading Ks

        // prefetch tiles for kt+1 (overlaps exp + O-MMA)
        if (kt < qt) {
            const int k1 = (kt + 1) * 128;
            const unsigned int vdst = vs_s + (((kt + 1) & 1) * QBUF) * 4;
            #pragma unroll
            for (int u = 0; u < 4; u++) {
                int r = pr + u * 32;
                cp_async16(ks_s + (r * ATT_LDQ + pc4) * 4, &Kb[(size_t)(k1 + r) * DHD + pc4]);
                cp_async16(vdst + (r * ATT_LDQ + pc4) * 4, &Vb[(size_t)(k1 + r) * DHD + pc4]);
            }
            cp_commit();
        }

        // exp (FMA-pipe poly) + causal mask + rowsum; e -> P and Ss
        {
            const int k0 = kt * 128;
            int r  = tid >> 2;
            int c0 = (tid & 3) * 32;
            int grow = m0 + r;
            float partial = 0.0f;
            #pragma unroll
            for (int c = 0; c < 32; c += 4) {
                int gc = k0 + c0 + c;
                float4 v = *(float4*)&Ss[r * ATT_LDS + c0 + c];
                v.x = (gc + 0 <= grow) ? fexp(v.x) : 0.0f;
                v.y = (gc + 1 <= grow) ? fexp(v.y) : 0.0f;
                v.z = (gc + 2 <= grow) ? fexp(v.z) : 0.0f;
                v.w = (gc + 3 <= grow) ? fexp(v.w) : 0.0f;
                partial += v.x + v.y + v.z + v.w;
                *(float4*)&Pb[(size_t)r * SS + gc] = v;
                *(float4*)&Ss[r * ATT_LDS + c0 + c] = v;
            }
            atomicAdd(&ls[r], partial);
        }
        __syncthreads();

        // O += e @ V  (warp tile 32x16)
        #pragma unroll
        for (int kk = 0; kk < 128; kk += 8) {
            wmma::fragment<wmma::matrix_a, 16, 16, 8, wmma::precision::tf32, wmma::row_major> a[2];
            wmma::fragment<wmma::matrix_b, 16, 16, 8, wmma::precision::tf32, wmma::row_major> b;
            #pragma unroll
            for (int i = 0; i < 2; i++)
                wmma::load_matrix_sync(a[i], &Ss[(wm * 32 + i * 16) * ATT_LDS + kk], ATT_LDS);
            wmma::load_matrix_sync(b, &Vs[cur + kk * ATT_LDQ + wn * 16], ATT_LDQ);
            #pragma unroll
            for (int i = 0; i < 2; i++)
                wmma::mma_sync(co[i], a[i], b, co[i]);
        }
        __syncthreads();
    }

    // zero-fill fully masked P region
    const int zc0 = (qt + 1) * 128;
    if (zc0 < SS) {
        const int rl4 = (SS - zc0) >> 2;
        const float4 z4 = make_float4(0.f, 0.f, 0.f, 0.f);
        for (int i = tid; i < 128 * rl4; i += 512) {
            int r = i / rl4, c4 = (i - r * rl4) * 4;
            *(float4*)&Pb[(size_t)r * SS + zc0 + c4] = z4;
        }
    }

    // stage O to smem, normalize, write AV
    #pragma unroll
    for (int i = 0; i < 2; i++)
        wmma::store_matrix_sync(&Ss[(wm * 32 + i * 16) * ATT_LDQ + wn * 16],
                                co[i], ATT_LDQ, wmma::mem_row_major);
    __syncthreads();

    const int bi = bh / HH, hi = bh % HH;
    {
        int r  = tid >> 2;
        int c0 = (tid & 3) * 16;
        float inv = 1.0f / ls[r];
        float* dst = AV + ((size_t)bi * SS + m0 + r) * DD + hi * DHD + c0;
        #pragma unroll
        for (int c = 0; c < 16; c += 4) {
            float4 v = *(float4*)&Ss[r * ATT_LDQ + c0 + c];
            v.x *= inv; v.y *= inv; v.z *= inv; v.w *= inv;
            *(float4*)&dst[c] = v;
        }
    }

    // rescale lower-triangle P by 1/rowsum
    {
        const int rl4 = zc0 >> 2;
        for (int i = tid; i < 128 * rl4; i += 512) {
            int r = i / rl4, c4 = (i - r * rl4) * 4;
            float inv = 1.0f / ls[r];
            float4 v = *(float4*)&Pb[(size_t)r * SS + c4];
            v.x *= inv; v.y *= inv; v.z *= inv; v.w *= inv;
            *(float4*)&Pb[(size_t)r * SS + c4] = v;
        }
    }
}

// ---------------- bias + exact GELU ----------------------------------------
__global__ void bias_gelu(float* __restrict__ F, const float* __restrict__ bias)
{
    const int idx4 = blockIdx.x * 256 + threadIdx.x;
    const size_t base = (size_t)idx4 * 4;
    float4 v = *(float4*)&F[base];
    const int col = (int)(base % DFF);
    float4 bb = *(const float4*)&bias[col];
    v.x += bb.x; v.y += bb.y; v.z += bb.z; v.w += bb.w;
    v.x = 0.5f * v.x * (1.0f + erff(v.x * 0.70710678118654752f));
    v.y = 0.5f * v.y * (1.0f + erff(v.y * 0.70710678118654752f));
    v.z = 0.5f * v.z * (1.0f + erff(v.z * 0.70710678118654752f));
    v.w = 0.5f * v.w * (1.0f + erff(v.w * 0.70710678118654752f));
    *(float4*)&F[base] = v;
}

// ---------------- fused residual add (+bias) + LayerNorm ------------------
__global__ void add_ln(const float* __restrict__ A, const float* __restrict__ Bv,
                       const float* __restrict__ bias,
                       const float* __restrict__ gamma, const float* __restrict__ beta,
                       float* __restrict__ out)
{
    const int row = blockIdx.x;
    const int tid = threadIdx.x;
    __shared__ float buf[DD];
    __shared__ float red[8];

    const float* a  = A  + (size_t)row * DD;
    const float* bp = Bv + (size_t)row * DD;

    float lsum = 0.f;
    #pragma unroll
    for (int i = 0; i < 3; i++) {
        int c = tid + i * 256;
        float v = a[c] + bp[c] + (bias ? bias[c] : 0.0f);
        buf[c] = v;
        lsum += v;
    }
    #pragma unroll
    for (int o = 16; o; o >>= 1) lsum += __shfl_xor_sync(0xffffffffu, lsum, o);
    if ((tid & 31) == 0) red[tid >> 5] = lsum;
    __syncthreads();
    float mu = (red[0]+red[1]+red[2]+red[3]+red[4]+red[5]+red[6]+red[7]) * (1.0f / DD);

    float lvar = 0.f;
    #pragma unroll
    for (int i = 0; i < 3; i++) {
        int c = tid + i * 256;
        float d = buf[c] - mu;
        lvar += d * d;
    }
    #pragma unroll
    for (int o = 16; o; o >>= 1) lvar += __shfl_xor_sync(0xffffffffu, lvar, o);
    __syncthreads();
    if ((tid & 31) == 0) red[tid >> 5] = lvar;
    __syncthreads();
    float var = (red[0]+red[1]+red[2]+red[3]+red[4]+red[5]+red[6]+red[7]) * (1.0f / DD);
    float inv = rsqrtf(var + 1e-5f);

    float* o = out + (size_t)row * DD;
    #pragma unroll
    for (int i = 0; i < 3; i++) {
        int c = tid + i * 256;
        o[c] = (buf[c] - mu) * inv * gamma[c] + beta[c];
    }
}

// ---------------------------------------------------------------------------
extern "C" void kernel_launch(void* const* d_in, const int* in_sizes, int n_in,
                              void* d_out, int out_size)
{
    const float* x   = (const float*)d_in[0];
    const float* Wq  = (const float*)d_in[2];
    const float* Wk  = (const float*)d_in[3];
    const float* Wv  = (const float*)d_in[4];
    const float* Wo  = (const float*)d_in[5];
    const float* bo  = (const float*)d_in[6];
    const float* g1  = (const float*)d_in[7];
    const float* b1  = (const float*)d_in[8];
    const float* W1  = (const float*)d_in[9];
    const float* bb1 = (const float*)d_in[10];
    const float* W2  = (const float*)d_in[11];
    const float* bb2 = (const float*)d_in[12];
    const float* g2  = (const float*)d_in[13];
    const float* b2  = (const float*)d_in[14];

    float* y = (float*)d_out;
    float* P = y + Y_ELEMS;

    float *qp, *kp, *vp, *avp, *aop, *hp, *f1p, *f2p;
    cudaGetSymbolAddress((void**)&qp,  g_q);
    cudaGetSymbolAddress((void**)&kp,  g_k);
    cudaGetSymbolAddress((void**)&vp,  g_v);
    cudaGetSymbolAddress((void**)&avp, g_av);
    cudaGetSymbolAddress((void**)&aop, g_ao);
    cudaGetSymbolAddress((void**)&hp,  g_h);
    cudaGetSymbolAddress((void**)&f1p, g_f1);
    cudaGetSymbolAddress((void**)&f2p, g_f2);

    cudaFuncSetAttribute(gemm_tc_nt, cudaFuncAttributeMaxDynamicSharedMemorySize,
                         GEMM_SMEM_BYTES);
    cudaFuncSetAttribute(qkv_gemm, cudaFuncAttributeMaxDynamicSharedMemorySize,
                         GEMM_SMEM_BYTES);
    static const size_t att_smem = (size_t)ATT_SMEM_FLOATS * sizeof(float);
    cudaFuncSetAttribute(attn_fused, cudaFuncAttributeMaxDynamicSharedMemorySize,
                         (int)att_smem);

    dim3 g768 (DD  / 128, MM / 128);
    dim3 g3072(DFF / 128, MM / 128);
    dim3 gqkv (DD  / 128, MM / 128, 3);

    // QKV projections: single merged launch, head-split outputs
    qkv_gemm<<<gqkv, 256, GEMM_SMEM_BYTES>>>(x, Wq, Wk, Wv, qp, kp, vp);

    // fused attention (cp.async pipelined, FMA-pipe exp)
    attn_fused<<<dim3(SS / 128, BB * HH), 512, att_smem>>>(qp, kp, vp, P, avp);

    // output projection (bias folded into add_ln)
    gemm_tc_nt<<<g768, 256, GEMM_SMEM_BYTES>>>(avp, Wo, aop, DD, DD);

    add_ln<<<MM, 256>>>(x, aop, bo, g1, b1, hp);

    gemm_tc_nt<<<g3072, 256, GEMM_SMEM_BYTES>>>(hp, W1, f1p, DFF, DD);
    bias_gelu<<<(int)((size_t)MM * DFF / 4 / 256), 256>>>(f1p, bb1);
    gemm_tc_nt<<<g768, 256, GEMM_SMEM_BYTES>>>(f1p, W2, f2p, DD, DFF);

    add_ln<<<MM, 256>>>(hp, f2p, bb2, g2, b2, y);
}

// round 12
// speedup vs baseline: 2.6329x; 1.8321x over previous
#include <cuda_runtime.h>
#include <cuda_fp16.h>
#include <cstdint>
#include <math.h>
#include <mma.h>

using namespace nvcuda;

// Problem constants
#define BB 2
#define SS 2048
#define HH 12
#define DHD 64
#define DD 768
#define DFF 3072
#define MM (BB*SS)
#define Y_ELEMS ((size_t)BB*SS*DD)

// ---------------- scratch (device globals) ---------------------------------
__device__ float g_q [BB*HH*SS*DHD];
__device__ float g_k [BB*HH*SS*DHD];
__device__ float g_v [BB*HH*SS*DHD];
__device__ float g_av[BB*SS*DD];
__device__ float g_ao[BB*SS*DD];
__device__ float g_h [BB*SS*DD];
__device__ float g_f2[BB*SS*DD];

// fp16 copies (GEMM inputs)
__device__ __half g_xh [BB*SS*DD];
__device__ __half g_wqh[DD*DD];
__device__ __half g_wkh[DD*DD];
__device__ __half g_wvh[DD*DD];
__device__ __half g_woh[DD*DD];
__device__ __half g_w1h[DFF*DD];
__device__ __half g_w2h[DD*DFF];
__device__ __half g_avh[BB*SS*DD];
__device__ __half g_hh [BB*SS*DD];
__device__ __half g_f1h[BB*SS*DFF];

__device__ __forceinline__ void cp_async16(unsigned int dst, const void* src) {
    asm volatile("cp.async.cg.shared.global [%0], [%1], 16;\n" :: "r"(dst), "l"(src));
}
__device__ __forceinline__ void cp_commit() {
    asm volatile("cp.async.commit_group;\n");
}
__device__ __forceinline__ void cp_wait0() {
    asm volatile("cp.async.wait_group 0;\n");
}
__device__ __forceinline__ void cp_wait1() {
    asm volatile("cp.async.wait_group 1;\n");
}

// FMA-pipe exp (neutral vs __expf; kept)
__device__ __forceinline__ float fexp(float x) {
    float t  = fmaxf(x, -80.0f) * 1.4426950408889634f;
    float fi = rintf(t);
    float f  = t - fi;
    float p  = 1.3393036e-3f;
    p = fmaf(p, f, 9.6181316e-3f);
    p = fmaf(p, f, 5.5504109e-2f);
    p = fmaf(p, f, 2.4022651e-1f);
    p = fmaf(p, f, 6.9314718e-1f);
    p = fmaf(p, f, 1.0f);
    return __int_as_float(__float_as_int(p) + ((int)fi << 23));
}

// ---------------- fp32 -> fp16 convert -------------------------------------
__global__ void f2h(const float* __restrict__ in, __half* __restrict__ out)
{
    const size_t i = ((size_t)blockIdx.x * 256 + threadIdx.x) * 4;
    float4 v = *(const float4*)&in[i];
    *(__half2*)&out[i]     = __floats2half2_rn(v.x, v.y);
    *(__half2*)&out[i + 2] = __floats2half2_rn(v.z, v.w);
}

// ============  fp16 NT GEMM, 3-stage cp.async pipeline  ====================
// A[M,K], B[N,K] half; fp32 accumulate. k-tile = 64 halfs (128B rows).
#define HLD 72
#define HBUF (128*HLD)                       // halfs per stage per matrix
#define GSTG 3
#define GEMMH_SMEM_BYTES (GSTG*2*HBUF*2)     // 110,592 B

// MODE 0: fp32 C row-major. MODE 2: bias+GELU -> half C. MODE 3: fp32 head-split.
template<int MODE>
__device__ __forceinline__ void gemm_h_body(const __half* __restrict__ A,
                                            const __half* __restrict__ B,
                                            const float* __restrict__ bias,
                                            void* __restrict__ Cv,
                                            int N, int K, int m0, int n0)
{
    extern __shared__ float gsm[];
    __half* As = (__half*)gsm;               // [GSTG][128][72]
    __half* Bs = As + GSTG*HBUF;

    const int tid  = threadIdx.x;            // 256
    const int warp = tid >> 5;
    const int wm   = warp & 1;               // 2 x 64 rows
    const int wn   = warp >> 1;              // 4 x 32 cols

    const unsigned int as_s = (unsigned int)__cvta_generic_to_shared(As);
    const unsigned int bs_s = (unsigned int)__cvta_generic_to_shared(Bs);

    wmma::fragment<wmma::accumulator, 16, 16, 16, float> c[4][2];
    #pragma unroll
    for (int i = 0; i < 4; i++)
        #pragma unroll
        for (int j = 0; j < 2; j++)
            wmma::fill_fragment(c[i][j], 0.0f);

    const int T = K >> 6;                    // 64-wide k-tiles

    auto issue = [&](int t) {
        const int k0 = t << 6;
        const unsigned int soff = (unsigned int)((t % GSTG) * HBUF * 2);
        #pragma unroll
        for (int i = 0; i < 4; i++) {
            int ch   = tid + i * 256;
            int row  = ch >> 3;
            int col8 = (ch & 7) * 8;
            cp_async16(as_s + soff + (unsigned int)((row * HLD + col8) * 2),
                       &A[(size_t)(m0 + row) * K + k0 + col8]);
            cp_async16(bs_s + soff + (unsigned int)((row * HLD + col8) * 2),
                       &B[(size_t)(n0 + row) * K + k0 + col8]);
        }
        cp_commit();
    };

    issue(0);
    if (T > 1) issue(1);

    for (int t = 0; t < T; t++) {
        if (t + 1 < T) cp_wait1(); else cp_wait0();
        __syncthreads();
        if (t + 2 < T) issue(t + 2);

        const int cur = (t % GSTG) * HBUF;
        #pragma unroll
        for (int kk = 0; kk < 64; kk += 16) {
            wmma::fragment<wmma::matrix_a, 16, 16, 16, __half, wmma::row_major> a[4];
            wmma::fragment<wmma::matrix_b, 16, 16, 16, __half, wmma::col_major> b[2];
            #pragma unroll
            for (int i = 0; i < 4; i++)
                wmma::load_matrix_sync(a[i], &As[cur + (wm * 64 + i * 16) * HLD + kk], HLD);
            #pragma unroll
            for (int j = 0; j < 2; j++)
                wmma::load_matrix_sync(b[j], &Bs[cur + (wn * 32 + j * 16) * HLD + kk], HLD);
            #pragma unroll
            for (int i = 0; i < 4; i++)
                #pragma unroll
                for (int j = 0; j < 2; j++)
                    wmma::mma_sync(c[i][j], a[i], b[j], c[i][j]);
        }
        __syncthreads();
    }

    if (MODE == 2) {
        float* stg = gsm;                    // [128][132] staging
        #pragma unroll
        for (int i = 0; i < 4; i++)
            #pragma unroll
            for (int j = 0; j < 2; j++)
                wmma::store_matrix_sync(&stg[(wm * 64 + i * 16) * 132 + wn * 32 + j * 16],
                                        c[i][j], 132, wmma::mem_row_major);
        __syncthreads();
        __half* C = (__half*)Cv;
        const int r  = tid >> 1;
        const int c0 = (tid & 1) * 64;
        #pragma unroll
        for (int cc = 0; cc < 64; cc += 4) {
            float4 v = *(float4*)&stg[r * 132 + c0 + cc];
            float4 bb = *(const float4*)&bias[n0 + c0 + cc];
            v.x += bb.x; v.y += bb.y; v.z += bb.z; v.w += bb.w;
            v.x = 0.5f * v.x * (1.0f + erff(v.x * 0.70710678118654752f));
            v.y = 0.5f * v.y * (1.0f + erff(v.y * 0.70710678118654752f));
            v.z = 0.5f * v.z * (1.0f + erff(v.z * 0.70710678118654752f));
            v.w = 0.5f * v.w * (1.0f + erff(v.w * 0.70710678118654752f));
            __half* dst = &C[(size_t)(m0 + r) * N + n0 + c0 + cc];
            *(__half2*)&dst[0] = __floats2half2_rn(v.x, v.y);
            *(__half2*)&dst[2] = __floats2half2_rn(v.z, v.w);
        }
    } else {
        float* C = (float*)Cv;
        #pragma unroll
        for (int i = 0; i < 4; i++) {
            int m = m0 + wm * 64 + i * 16;
            #pragma unroll
            for (int j = 0; j < 2; j++) {
                int n = n0 + wn * 32 + j * 16;
                if (MODE == 3) {
                    int bidx = m >> 11, s = m & 2047;
                    int h = n >> 6, dh = n & 63;
                    float* dst = C + (((size_t)(bidx * HH + h)) * SS + s) * DHD + dh;
                    wmma::store_matrix_sync(dst, c[i][j], DHD, wmma::mem_row_major);
                } else {
                    wmma::store_matrix_sync(C + (size_t)m * N + n, c[i][j], N, wmma::mem_row_major);
                }
            }
        }
    }
}

__global__ void __launch_bounds__(256)
gemm_h(const __half* __restrict__ A, const __half* __restrict__ B,
       float* __restrict__ C, int N, int K)
{
    gemm_h_body<0>(A, B, nullptr, C, N, K, blockIdx.y * 128, blockIdx.x * 128);
}

__global__ void __launch_bounds__(256)
gemm_h_gelu(const __half* __restrict__ A, const __half* __restrict__ B,
            const float* __restrict__ bias, __half* __restrict__ C, int N, int K)
{
    gemm_h_body<2>(A, B, bias, C, N, K, blockIdx.y * 128, blockIdx.x * 128);
}

__global__ void __launch_bounds__(256)
qkv_gemm_h(const __half* __restrict__ X,
           const __half* __restrict__ Wq, const __half* __restrict__ Wk,
           const __half* __restrict__ Wv,
           float* __restrict__ Qo, float* __restrict__ Ko, float* __restrict__ Vo)
{
    const __half* B = (blockIdx.z == 0) ? Wq : (blockIdx.z == 1) ? Wk : Wv;
    float*        C = (blockIdx.z == 0) ? Qo : (blockIdx.z == 1) ? Ko : Vo;
    gemm_h_body<3>(X, B, nullptr, C, DD, DD, blockIdx.y * 128, blockIdx.x * 128);
}

// ==============  fused flash attention (tf32, cp.async) — proven  ==========
#define ATT_LDQ 68
#define QBUF (128*ATT_LDQ)
#define ATT_LDS 132
#define ATT_SMEM_FLOATS (4*QBUF + 128*ATT_LDS + 128)

__global__ void __launch_bounds__(512, 1)
attn_fused(const float* __restrict__ Q, const float* __restrict__ K,
           const float* __restrict__ V, float* __restrict__ P,
           float* __restrict__ AV, __half* __restrict__ AVh)
{
    extern __shared__ float sm[];
    float* Qs = sm;
    float* Ks = Qs + QBUF;
    float* Vs = Ks + QBUF;          // [2][128][68]
    float* Ss = Vs + 2*QBUF;        // [128][132]
    float* ls = Ss + 128 * ATT_LDS;

    const int bh  = blockIdx.y;
    const int qt  = gridDim.x - 1 - blockIdx.x;
    const int m0  = qt * 128;
    const int tid = threadIdx.x;
    const int warp = tid >> 5;
    const int wm = warp & 3;
    const int wn = warp >> 2;

    const float* Qb = Q + ((size_t)bh * SS + m0) * DHD;
    const float* Kb = K + (size_t)bh * SS * DHD;
    const float* Vb = V + (size_t)bh * SS * DHD;
    float* Pb = P + ((size_t)bh * SS + m0) * SS;

    const int pr  = tid >> 4;
    const int pc4 = (tid & 15) * 4;
    const unsigned int ks_s = (unsigned int)__cvta_generic_to_shared(Ks);
    const unsigned int vs_s = (unsigned int)__cvta_generic_to_shared(Vs);

    for (int i = tid; i < 128 * 16; i += 512) {
        int r = i >> 4, c4 = (i & 15) * 4;
        float4 v = *(const float4*)&Qb[(size_t)r * DHD + c4];
        v.x *= 0.125f; v.y *= 0.125f; v.z *= 0.125f; v.w *= 0.125f;
        *(float4*)&Qs[r * ATT_LDQ + c4] = v;
    }
    if (tid < 128) ls[tid] = 0.0f;

    #pragma unroll
    for (int u = 0; u < 4; u++) {
        int r = pr + u * 32;
        cp_async16(ks_s + (r * ATT_LDQ + pc4) * 4, &Kb[(size_t)r * DHD + pc4]);
        cp_async16(vs_s + (r * ATT_LDQ + pc4) * 4, &Vb[(size_t)r * DHD + pc4]);
    }
    cp_commit();

    wmma::fragment<wmma::accumulator, 16, 16, 8, float> co[2];
    #pragma unroll
    for (int i = 0; i < 2; i++) wmma::fill_fragment(co[i], 0.0f);

    for (int kt = 0; kt <= qt; kt++) {
        const int cur = (kt & 1) * QBUF;
        cp_wait0();
        __syncthreads();

        wmma::fragment<wmma::accumulator, 16, 16, 8, float> cs[2][2];
        #pragma unroll
        for (int i = 0; i < 2; i++)
            #pragma unroll
            for (int j = 0; j < 2; j++)
                wmma::fill_fragment(cs[i][j], 0.0f);

        #pragma unroll
        for (int kk = 0; kk < 64; kk += 8) {
            wmma::fragment<wmma::matrix_a, 16, 16, 8, wmma::precision::tf32, wmma::row_major> a[2];
            wmma::fragment<wmma::matrix_b, 16, 16, 8, wmma::precision::tf32, wmma::col_major> b[2];
            #pragma unroll
            for (int i = 0; i < 2; i++)
                wmma::load_matrix_sync(a[i], &Qs[(wm * 32 + i * 16) * ATT_LDQ + kk], ATT_LDQ);
            #pragma unroll
            for (int j = 0; j < 2; j++)
                wmma::load_matrix_sync(b[j], &Ks[(wn * 32 + j * 16) * ATT_LDQ + kk], ATT_LDQ);
            #pragma unroll
            for (int i = 0; i < 2; i++)
                #pragma unroll
                for (int j = 0; j < 2; j++)
                    wmma::mma_sync(cs[i][j], a[i], b[j], cs[i][j]);
        }
        #pragma unroll
        for (int i = 0; i < 2; i++)
            #pragma unroll
            for (int j = 0; j < 2; j++)
                wmma::store_matrix_sync(&Ss[(wm * 32 + i * 16) * ATT_LDS + wn * 32 + j * 16],
                                        cs[i][j], ATT_LDS, wmma::mem_row_major);
        __syncthreads();

        if (kt < qt) {
            const int k1 = (kt + 1) * 128;
            const unsigned int vdst = vs_s + (((kt + 1) & 1) * QBUF) * 4;
            #pragma unroll
            for (int u = 0; u < 4; u++) {
                int r = pr + u * 32;
                cp_async16(ks_s + (r * ATT_LDQ + pc4) * 4, &Kb[(size_t)(k1 + r) * DHD + pc4]);
                cp_async16(vdst + (r * ATT_LDQ + pc4) * 4, &Vb[(size_t)(k1 + r) * DHD + pc4]);
            }
            cp_commit();
        }

        {
            const int k0 = kt * 128;
            int r  = tid >> 2;
            int c0 = (tid & 3) * 32;
            int grow = m0 + r;
            float partial = 0.0f;
            #pragma unroll
            for (int c = 0; c < 32; c += 4) {
                int gc = k0 + c0 + c;
                float4 v = *(float4*)&Ss[r * ATT_LDS + c0 + c];
                v.x = (gc + 0 <= grow) ? fexp(v.x) : 0.0f;
                v.y = (gc + 1 <= grow) ? fexp(v.y) : 0.0f;
                v.z = (gc + 2 <= grow) ? fexp(v.z) : 0.0f;
                v.w = (gc + 3 <= grow) ? fexp(v.w) : 0.0f;
                partial += v.x + v.y + v.z + v.w;
                *(float4*)&Pb[(size_t)r * SS + gc] = v;
                *(float4*)&Ss[r * ATT_LDS + c0 + c] = v;
            }
            atomicAdd(&ls[r], partial);
        }
        __syncthreads();

        #pragma unroll
        for (int kk = 0; kk < 128; kk += 8) {
            wmma::fragment<wmma::matrix_a, 16, 16, 8, wmma::precision::tf32, wmma::row_major> a[2];
            wmma::fragment<wmma::matrix_b, 16, 16, 8, wmma::precision::tf32, wmma::row_major> b;
            #pragma unroll
            for (int i = 0; i < 2; i++)
                wmma::load_matrix_sync(a[i], &Ss[(wm * 32 + i * 16) * ATT_LDS + kk], ATT_LDS);
            wmma::load_matrix_sync(b, &Vs[cur + kk * ATT_LDQ + wn * 16], ATT_LDQ);
            #pragma unroll
            for (int i = 0; i < 2; i++)
                wmma::mma_sync(co[i], a[i], b, co[i]);
        }
        __syncthreads();
    }

    const int zc0 = (qt + 1) * 128;
    if (zc0 < SS) {
        const int rl4 = (SS - zc0) >> 2;
        const float4 z4 = make_float4(0.f, 0.f, 0.f, 0.f);
        for (int i = tid; i < 128 * rl4; i += 512) {
            int r = i / rl4, c4 = (i - r * rl4) * 4;
            *(float4*)&Pb[(size_t)r * SS + zc0 + c4] = z4;
        }
    }

    #pragma unroll
    for (int i = 0; i < 2; i++)
        wmma::store_matrix_sync(&Ss[(wm * 32 + i * 16) * ATT_LDQ + wn * 16],
                                co[i], ATT_LDQ, wmma::mem_row_major);
    __syncthreads();

    const int bi = bh / HH, hi = bh % HH;
    {
        int r  = tid >> 2;
        int c0 = (tid & 3) * 16;
        float inv = 1.0f / ls[r];
        size_t base = ((size_t)bi * SS + m0 + r) * DD + hi * DHD + c0;
        float*  dst  = AV  + base;
        __half* dsth = AVh + base;
        #pragma unroll
        for (int c = 0; c < 16; c += 4) {
            float4 v = *(float4*)&Ss[r * ATT_LDQ + c0 + c];
            v.x *= inv; v.y *= inv; v.z *= inv; v.w *= inv;
            *(float4*)&dst[c] = v;
            *(__half2*)&dsth[c]     = __floats2half2_rn(v.x, v.y);
            *(__half2*)&dsth[c + 2] = __floats2half2_rn(v.z, v.w);
        }
    }

    {
        const int rl4 = zc0 >> 2;
        for (int i = tid; i < 128 * rl4; i += 512) {
            int r = i / rl4, c4 = (i - r * rl4) * 4;
            float inv = 1.0f / ls[r];
            float4 v = *(float4*)&Pb[(size_t)r * SS + c4];
            v.x *= inv; v.y *= inv; v.z *= inv; v.w *= inv;
            *(float4*)&Pb[(size_t)r * SS + c4] = v;
        }
    }
}

// ---------------- fused residual add (+bias) + LayerNorm (+half copy) ------
__global__ void add_ln(const float* __restrict__ A, const float* __restrict__ Bv,
                       const float* __restrict__ bias,
                       const float* __restrict__ gamma, const float* __restrict__ beta,
                       float* __restrict__ out, __half* __restrict__ outh)
{
    const int row = blockIdx.x;
    const int tid = threadIdx.x;
    __shared__ float buf[DD];
    __shared__ float red[8];

    const float* a  = A  + (size_t)row * DD;
    const float* bp = Bv + (size_t)row * DD;

    float lsum = 0.f;
    #pragma unroll
    for (int i = 0; i < 3; i++) {
        int c = tid + i * 256;
        float v = a[c] + bp[c] + (bias ? bias[c] : 0.0f);
        buf[c] = v;
        lsum += v;
    }
    #pragma unroll
    for (int o = 16; o; o >>= 1) lsum += __shfl_xor_sync(0xffffffffu, lsum, o);
    if ((tid & 31) == 0) red[tid >> 5] = lsum;
    __syncthreads();
    float mu = (red[0]+red[1]+red[2]+red[3]+red[4]+red[5]+red[6]+red[7]) * (1.0f / DD);

    float lvar = 0.f;
    #pragma unroll
    for (int i = 0; i < 3; i++) {
        int c = tid + i * 256;
        float d = buf[c] - mu;
        lvar += d * d;
    }
    #pragma unroll
    for (int o = 16; o; o >>= 1) lvar += __shfl_xor_sync(0xffffffffu, lvar, o);
    __syncthreads();
    if ((tid & 31) == 0) red[tid >> 5] = lvar;
    __syncthreads();
    float var = (red[0]+red[1]+red[2]+red[3]+red[4]+red[5]+red[6]+red[7]) * (1.0f / DD);
    float inv = rsqrtf(var + 1e-5f);

    float* o = out + (size_t)row * DD;
    __half* oh = outh ? outh + (size_t)row * DD : nullptr;
    #pragma unroll
    for (int i = 0; i < 3; i++) {
        int c = tid + i * 256;
        float v = (buf[c] - mu) * inv * gamma[c] + beta[c];
        o[c] = v;
        if (oh) oh[c] = __float2half_rn(v);
    }
}

// ---------------------------------------------------------------------------
extern "C" void kernel_launch(void* const* d_in, const int* in_sizes, int n_in,
                              void* d_out, int out_size)
{
    const float* x   = (const float*)d_in[0];
    const float* Wq  = (const float*)d_in[2];
    const float* Wk  = (const float*)d_in[3];
    const float* Wv  = (const float*)d_in[4];
    const float* Wo  = (const float*)d_in[5];
    const float* bo  = (const float*)d_in[6];
    const float* g1  = (const float*)d_in[7];
    const float* b1  = (const float*)d_in[8];
    const float* W1  = (const float*)d_in[9];
    const float* bb1 = (const float*)d_in[10];
    const float* W2  = (const float*)d_in[11];
    const float* bb2 = (const float*)d_in[12];
    const float* g2  = (const float*)d_in[13];
    const float* b2  = (const float*)d_in[14];

    float* y = (float*)d_out;
    float* P = y + Y_ELEMS;

    float *qp, *kp, *vp, *avp, *aop, *hp, *f2p;
    __half *xh, *wqh, *wkh, *wvh, *woh, *w1h, *w2h, *avh, *hh, *f1h;
    cudaGetSymbolAddress((void**)&qp,  g_q);
    cudaGetSymbolAddress((void**)&kp,  g_k);
    cudaGetSymbolAddress((void**)&vp,  g_v);
    cudaGetSymbolAddress((void**)&avp, g_av);
    cudaGetSymbolAddress((void**)&aop, g_ao);
    cudaGetSymbolAddress((void**)&hp,  g_h);
    cudaGetSymbolAddress((void**)&f2p, g_f2);
    cudaGetSymbolAddress((void**)&xh,  g_xh);
    cudaGetSymbolAddress((void**)&wqh, g_wqh);
    cudaGetSymbolAddress((void**)&wkh, g_wkh);
    cudaGetSymbolAddress((void**)&wvh, g_wvh);
    cudaGetSymbolAddress((void**)&woh, g_woh);
    cudaGetSymbolAddress((void**)&w1h, g_w1h);
    cudaGetSymbolAddress((void**)&w2h, g_w2h);
    cudaGetSymbolAddress((void**)&avh, g_avh);
    cudaGetSymbolAddress((void**)&hh,  g_hh);
    cudaGetSymbolAddress((void**)&f1h, g_f1h);

    cudaFuncSetAttribute(gemm_h, cudaFuncAttributeMaxDynamicSharedMemorySize, GEMMH_SMEM_BYTES);
    cudaFuncSetAttribute(gemm_h_gelu, cudaFuncAttributeMaxDynamicSharedMemorySize, GEMMH_SMEM_BYTES);
    cudaFuncSetAttribute(qkv_gemm_h, cudaFuncAttributeMaxDynamicSharedMemorySize, GEMMH_SMEM_BYTES);
    static const size_t att_smem = (size_t)ATT_SMEM_FLOATS * sizeof(float);
    cudaFuncSetAttribute(attn_fused, cudaFuncAttributeMaxDynamicSharedMemorySize, (int)att_smem);

    // fp16 conversions (x + all weights)
    f2h<<<(MM*DD)/1024, 256>>>(x,  xh);
    f2h<<<(DD*DD)/1024, 256>>>(Wq, wqh);
    f2h<<<(DD*DD)/1024, 256>>>(Wk, wkh);
    f2h<<<(DD*DD)/1024, 256>>>(Wv, wvh);
    f2h<<<(DD*DD)/1024, 256>>>(Wo, woh);
    f2h<<<(DFF*DD)/1024, 256>>>(W1, w1h);
    f2h<<<(DD*DFF)/1024, 256>>>(W2, w2h);

    dim3 g768 (DD  / 128, MM / 128);
    dim3 g3072(DFF / 128, MM / 128);
    dim3 gqkv (DD  / 128, MM / 128, 3);

    // QKV projections (fp16 in, fp32 head-split out)
    qkv_gemm_h<<<gqkv, 256, GEMMH_SMEM_BYTES>>>(xh, wqh, wkh, wvh, qp, kp, vp);

    // fused attention (tf32) -> P, AV fp32 + fp16
    attn_fused<<<dim3(SS / 128, BB * HH), 512, att_smem>>>(qp, kp, vp, P, avp, avh);

    // output projection (fp16 in, fp32 out)
    gemm_h<<<g768, 256, GEMMH_SMEM_BYTES>>>(avh, woh, aop, DD, DD);

    // h = LN(x + attn_out + bo) -> fp32 + fp16
    add_ln<<<MM, 256>>>(x, aop, bo, g1, b1, hp, hh);

    // FFN1 + bias + GELU fused -> fp16
    gemm_h_gelu<<<g3072, 256, GEMMH_SMEM_BYTES>>>(hh, w1h, bb1, f1h, DFF, DD);

    // FFN2 (fp16 in, fp32 out)
    gemm_h<<<g768, 256, GEMMH_SMEM_BYTES>>>(f1h, w2h, f2p, DD, DFF);

    // y = LN(h + f + bb2)
    add_ln<<<MM, 256>>>(hp, f2p, bb2, g2, b2, y, nullptr);
}

// round 13
// speedup vs baseline: 3.4728x; 1.3190x over previous
#include <cuda_runtime.h>
#include <cuda_fp16.h>
#include <cstdint>
#include <math.h>
#include <mma.h>

using namespace nvcuda;

// Problem constants
#define BB 2
#define SS 2048
#define HH 12
#define DHD 64
#define DD 768
#define DFF 3072
#define MM (BB*SS)
#define Y_ELEMS ((size_t)BB*SS*DD)

// ---------------- scratch (device globals) ---------------------------------
__device__ float g_ao[BB*SS*DD];
__device__ float g_h [BB*SS*DD];
__device__ float g_f2[BB*SS*DD];

// fp16 buffers
__device__ __half g_qh [BB*HH*SS*DHD];
__device__ __half g_kh [BB*HH*SS*DHD];
__device__ __half g_vh [BB*HH*SS*DHD];
__device__ __half g_xh [BB*SS*DD];
__device__ __half g_wqh[DD*DD];
__device__ __half g_wkh[DD*DD];
__device__ __half g_wvh[DD*DD];
__device__ __half g_woh[DD*DD];
__device__ __half g_w1h[DFF*DD];
__device__ __half g_w2h[DD*DFF];
__device__ __half g_avh[BB*SS*DD];
__device__ __half g_hh [BB*SS*DD];
__device__ __half g_f1h[BB*SS*DFF];

__device__ __forceinline__ void cp_async16(unsigned int dst, const void* src) {
    asm volatile("cp.async.cg.shared.global [%0], [%1], 16;\n" :: "r"(dst), "l"(src));
}
__device__ __forceinline__ void cp_commit() {
    asm volatile("cp.async.commit_group;\n");
}
__device__ __forceinline__ void cp_wait0() {
    asm volatile("cp.async.wait_group 0;\n");
}
__device__ __forceinline__ void cp_wait1() {
    asm volatile("cp.async.wait_group 1;\n");
}

// FMA-pipe exp of (x * 1/8), x in raw-score units. t = x*log2(e)/8.
__device__ __forceinline__ float fexp8(float x) {
    float t  = fmaxf(x * 0.18033688011112042f, -115.0f);
    float fi = rintf(t);
    float f  = t - fi;
    float p  = 1.3393036e-3f;
    p = fmaf(p, f, 9.6181316e-3f);
    p = fmaf(p, f, 5.5504109e-2f);
    p = fmaf(p, f, 2.4022651e-1f);
    p = fmaf(p, f, 6.9314718e-1f);
    p = fmaf(p, f, 1.0f);
    return __int_as_float(__float_as_int(p) + ((int)fi << 23));
}

// ---------------- fp32 -> fp16 convert -------------------------------------
__global__ void f2h(const float* __restrict__ in, __half* __restrict__ out)
{
    const size_t i = ((size_t)blockIdx.x * 256 + threadIdx.x) * 4;
    float4 v = *(const float4*)&in[i];
    *(__half2*)&out[i]     = __floats2half2_rn(v.x, v.y);
    *(__half2*)&out[i + 2] = __floats2half2_rn(v.z, v.w);
}

// ============  fp16 NT GEMM, 3-stage cp.async pipeline  ====================
#define HLD 72
#define HBUF (128*HLD)
#define GSTG 3
#define GEMMH_SMEM_BYTES (GSTG*2*HBUF*2)     // 110,592 B

// MODE 0: fp32 C. MODE 2: bias+GELU -> half C. MODE 4: head-split half C.
template<int MODE>
__device__ __forceinline__ void gemm_h_body(const __half* __restrict__ A,
                                            const __half* __restrict__ B,
                                            const float* __restrict__ bias,
                                            void* __restrict__ Cv,
                                            int N, int K, int m0, int n0)
{
    extern __shared__ float gsm[];
    __half* As = (__half*)gsm;               // [GSTG][128][72]
    __half* Bs = As + GSTG*HBUF;

    const int tid  = threadIdx.x;            // 256
    const int warp = tid >> 5;
    const int wm   = warp & 1;
    const int wn   = warp >> 1;

    const unsigned int as_s = (unsigned int)__cvta_generic_to_shared(As);
    const unsigned int bs_s = (unsigned int)__cvta_generic_to_shared(Bs);

    wmma::fragment<wmma::accumulator, 16, 16, 16, float> c[4][2];
    #pragma unroll
    for (int i = 0; i < 4; i++)
        #pragma unroll
        for (int j = 0; j < 2; j++)
            wmma::fill_fragment(c[i][j], 0.0f);

    const int T = K >> 6;

    auto issue = [&](int t) {
        const int k0 = t << 6;
        const unsigned int soff = (unsigned int)((t % GSTG) * HBUF * 2);
        #pragma unroll
        for (int i = 0; i < 4; i++) {
            int ch   = tid + i * 256;
            int row  = ch >> 3;
            int col8 = (ch & 7) * 8;
            cp_async16(as_s + soff + (unsigned int)((row * HLD + col8) * 2),
                       &A[(size_t)(m0 + row) * K + k0 + col8]);
            cp_async16(bs_s + soff + (unsigned int)((row * HLD + col8) * 2),
                       &B[(size_t)(n0 + row) * K + k0 + col8]);
        }
        cp_commit();
    };

    issue(0);
    if (T > 1) issue(1);

    for (int t = 0; t < T; t++) {
        if (t + 1 < T) cp_wait1(); else cp_wait0();
        __syncthreads();
        if (t + 2 < T) issue(t + 2);

        const int cur = (t % GSTG) * HBUF;
        #pragma unroll
        for (int kk = 0; kk < 64; kk += 16) {
            wmma::fragment<wmma::matrix_a, 16, 16, 16, __half, wmma::row_major> a[4];
            wmma::fragment<wmma::matrix_b, 16, 16, 16, __half, wmma::col_major> b[2];
            #pragma unroll
            for (int i = 0; i < 4; i++)
                wmma::load_matrix_sync(a[i], &As[cur + (wm * 64 + i * 16) * HLD + kk], HLD);
            #pragma unroll
            for (int j = 0; j < 2; j++)
                wmma::load_matrix_sync(b[j], &Bs[cur + (wn * 32 + j * 16) * HLD + kk], HLD);
            #pragma unroll
            for (int i = 0; i < 4; i++)
                #pragma unroll
                for (int j = 0; j < 2; j++)
                    wmma::mma_sync(c[i][j], a[i], b[j], c[i][j]);
        }
        __syncthreads();
    }

    if (MODE == 2 || MODE == 4) {
        float* stg = gsm;                    // [128][132]
        #pragma unroll
        for (int i = 0; i < 4; i++)
            #pragma unroll
            for (int j = 0; j < 2; j++)
                wmma::store_matrix_sync(&stg[(wm * 64 + i * 16) * 132 + wn * 32 + j * 16],
                                        c[i][j], 132, wmma::mem_row_major);
        __syncthreads();
        __half* C = (__half*)Cv;
        const int r  = tid >> 1;
        const int c0 = (tid & 1) * 64;
        if (MODE == 2) {
            #pragma unroll
            for (int cc = 0; cc < 64; cc += 4) {
                float4 v = *(float4*)&stg[r * 132 + c0 + cc];
                float4 bb = *(const float4*)&bias[n0 + c0 + cc];
                v.x += bb.x; v.y += bb.y; v.z += bb.z; v.w += bb.w;
                v.x = 0.5f * v.x * (1.0f + erff(v.x * 0.70710678118654752f));
                v.y = 0.5f * v.y * (1.0f + erff(v.y * 0.70710678118654752f));
                v.z = 0.5f * v.z * (1.0f + erff(v.z * 0.70710678118654752f));
                v.w = 0.5f * v.w * (1.0f + erff(v.w * 0.70710678118654752f));
                __half* dst = &C[(size_t)(m0 + r) * N + n0 + c0 + cc];
                *(__half2*)&dst[0] = __floats2half2_rn(v.x, v.y);
                *(__half2*)&dst[2] = __floats2half2_rn(v.z, v.w);
            }
        } else {
            // head-split half: row m -> (b,s), col block -> (h, dh 0..63)
            int m = m0 + r;
            int bidx = m >> 11, s = m & 2047;
            int h = (n0 + c0) >> 6;
            __half* dst = &C[(((size_t)(bidx * HH + h)) * SS + s) * DHD];
            #pragma unroll
            for (int cc = 0; cc < 64; cc += 4) {
                float4 v = *(float4*)&stg[r * 132 + c0 + cc];
                *(__half2*)&dst[cc]     = __floats2half2_rn(v.x, v.y);
                *(__half2*)&dst[cc + 2] = __floats2half2_rn(v.z, v.w);
            }
        }
    } else {
        float* C = (float*)Cv;
        #pragma unroll
        for (int i = 0; i < 4; i++) {
            int m = m0 + wm * 64 + i * 16;
            #pragma unroll
            for (int j = 0; j < 2; j++) {
                int n = n0 + wn * 32 + j * 16;
                wmma::store_matrix_sync(C + (size_t)m * N + n, c[i][j], N, wmma::mem_row_major);
            }
        }
    }
}

__global__ void __launch_bounds__(256)
gemm_h(const __half* __restrict__ A, const __half* __restrict__ B,
       float* __restrict__ C, int N, int K)
{
    gemm_h_body<0>(A, B, nullptr, C, N, K, blockIdx.y * 128, blockIdx.x * 128);
}

__global__ void __launch_bounds__(256)
gemm_h_gelu(const __half* __restrict__ A, const __half* __restrict__ B,
            const float* __restrict__ bias, __half* __restrict__ C, int N, int K)
{
    gemm_h_body<2>(A, B, bias, C, N, K, blockIdx.y * 128, blockIdx.x * 128);
}

__global__ void __launch_bounds__(256)
qkv_gemm_h(const __half* __restrict__ X,
           const __half* __restrict__ Wq, const __half* __restrict__ Wk,
           const __half* __restrict__ Wv,
           __half* __restrict__ Qo, __half* __restrict__ Ko, __half* __restrict__ Vo)
{
    const __half* B = (blockIdx.z == 0) ? Wq : (blockIdx.z == 1) ? Wk : Wv;
    __half*       C = (blockIdx.z == 0) ? Qo : (blockIdx.z == 1) ? Ko : Vo;
    gemm_h_body<4>(X, B, nullptr, C, DD, DD, blockIdx.y * 128, blockIdx.x * 128);
}

// ==============  fused flash attention, fp16 MMA, cp.async  ================
// smem layout (bytes):
//   Qh  [128][72] half   @ 0        (18,432)
//   Kh  [128][72] half   @ 18432    (18,432)
//   Vh  [2][128][72]     @ 36864    (36,864)
//   Ss  [128][132] float @ 73728    (67,584)
//   Es  [128][136] half  @ 141312   (34,816)
//   ls  [128] float      @ 176128   (512)
#define AT_QH 0
#define AT_KH 18432
#define AT_VH 36864
#define AT_SS 73728
#define AT_ES 141312
#define AT_LS 176128
#define ATT_SMEM_BYTES 176640
#define HLDA 72
#define HBUFA (128*HLDA)

__global__ void __launch_bounds__(512, 1)
attn_fused(const __half* __restrict__ Q, const __half* __restrict__ K,
           const __half* __restrict__ V, float* __restrict__ P,
           __half* __restrict__ AVh)
{
    extern __shared__ char smraw[];
    __half* Qh = (__half*)(smraw + AT_QH);
    __half* Kh = (__half*)(smraw + AT_KH);
    __half* Vh = (__half*)(smraw + AT_VH);
    float*  Ss = (float*)(smraw + AT_SS);
    __half* Es = (__half*)(smraw + AT_ES);
    float*  ls = (float*)(smraw + AT_LS);

    const int bh  = blockIdx.y;
    const int qt  = gridDim.x - 1 - blockIdx.x;
    const int m0  = qt * 128;
    const int tid = threadIdx.x;
    const int warp = tid >> 5;
    const int wm = warp & 3;
    const int wn = warp >> 2;

    const __half* Qb = Q + ((size_t)bh * SS + m0) * DHD;
    const __half* Kb = K + (size_t)bh * SS * DHD;
    const __half* Vb = V + (size_t)bh * SS * DHD;
    float* Pb = P + ((size_t)bh * SS + m0) * SS;

    // cp.async: per tile 128 rows x 128B = 1024 x 16B chunks; 2 per thread
    const unsigned int kh_s = (unsigned int)__cvta_generic_to_shared(Kh);
    const unsigned int vh_s = (unsigned int)__cvta_generic_to_shared(Vh);

    // load Q tile (fp16, no scaling — folded into exp)
    for (int ch = tid; ch < 1024; ch += 512) {
        int r = ch >> 3, c8 = (ch & 7) * 8;
        *(uint4*)&Qh[r * HLDA + c8] = *(const uint4*)&Qb[(size_t)r * DHD + c8];
    }
    if (tid < 128) ls[tid] = 0.0f;

    // issue copies for kt = 0
    #pragma unroll
    for (int u = 0; u < 2; u++) {
        int ch = tid + u * 512;
        int r = ch >> 3, c8 = (ch & 7) * 8;
        cp_async16(kh_s + (unsigned int)((r * HLDA + c8) * 2), &Kb[(size_t)r * DHD + c8]);
        cp_async16(vh_s + (unsigned int)((r * HLDA + c8) * 2), &Vb[(size_t)r * DHD + c8]);
    }
    cp_commit();

    wmma::fragment<wmma::accumulator, 16, 16, 16, float> co[2];
    #pragma unroll
    for (int i = 0; i < 2; i++) wmma::fill_fragment(co[i], 0.0f);

    for (int kt = 0; kt <= qt; kt++) {
        const int vcur = (kt & 1) * HBUFA;
        cp_wait0();
        __syncthreads();

        // S = Q @ K^T  (fp16 MMA, warp tile 32x32, k=64)
        wmma::fragment<wmma::accumulator, 16, 16, 16, float> cs[2][2];
        #pragma unroll
        for (int i = 0; i < 2; i++)
            #pragma unroll
            for (int j = 0; j < 2; j++)
                wmma::fill_fragment(cs[i][j], 0.0f);

        #pragma unroll
        for (int kk = 0; kk < 64; kk += 16) {
            wmma::fragment<wmma::matrix_a, 16, 16, 16, __half, wmma::row_major> a[2];
            wmma::fragment<wmma::matrix_b, 16, 16, 16, __half, wmma::col_major> b[2];
            #pragma unroll
            for (int i = 0; i < 2; i++)
                wmma::load_matrix_sync(a[i], &Qh[(wm * 32 + i * 16) * HLDA + kk], HLDA);
            #pragma unroll
            for (int j = 0; j < 2; j++)
                wmma::load_matrix_sync(b[j], &Kh[(wn * 32 + j * 16) * HLDA + kk], HLDA);
            #pragma unroll
            for (int i = 0; i < 2; i++)
                #pragma unroll
                for (int j = 0; j < 2; j++)
                    wmma::mma_sync(cs[i][j], a[i], b[j], cs[i][j]);
        }
        #pragma unroll
        for (int i = 0; i < 2; i++)
            #pragma unroll
            for (int j = 0; j < 2; j++)
                wmma::store_matrix_sync(&Ss[(wm * 32 + i * 16) * 132 + wn * 32 + j * 16],
                                        cs[i][j], 132, wmma::mem_row_major);
        __syncthreads();   // Ss visible; all warps done reading Kh

        // prefetch tiles for kt+1 (overlaps exp + O-MMA)
        if (kt < qt) {
            const int k1 = (kt + 1) * 128;
            const unsigned int vdst = vh_s + (unsigned int)((((kt + 1) & 1) * HBUFA) * 2);
            #pragma unroll
            for (int u = 0; u < 2; u++) {
                int ch = tid + u * 512;
                int r = ch >> 3, c8 = (ch & 7) * 8;
                cp_async16(kh_s + (unsigned int)((r * HLDA + c8) * 2),
                           &Kb[(size_t)(k1 + r) * DHD + c8]);
                cp_async16(vdst + (unsigned int)((r * HLDA + c8) * 2),
                           &Vb[(size_t)(k1 + r) * DHD + c8]);
            }
            cp_commit();
        }

        // e = exp(s/8) + causal mask + rowsum; fp32 e -> P, fp16 e -> Es
        {
            const int k0 = kt * 128;
            int r  = tid >> 2;
            int c0 = (tid & 3) * 32;
            int grow = m0 + r;
            float partial = 0.0f;
            #pragma unroll
            for (int c = 0; c < 32; c += 4) {
                int gc = k0 + c0 + c;
                float4 v = *(float4*)&Ss[r * 132 + c0 + c];
                v.x = (gc + 0 <= grow) ? fexp8(v.x) : 0.0f;
                v.y = (gc + 1 <= grow) ? fexp8(v.y) : 0.0f;
                v.z = (gc + 2 <= grow) ? fexp8(v.z) : 0.0f;
                v.w = (gc + 3 <= grow) ? fexp8(v.w) : 0.0f;
                partial += v.x + v.y + v.z + v.w;
                *(float4*)&Pb[(size_t)r * SS + gc] = v;
                __half* ed = &Es[r * 136 + c0 + c];
                *(__half2*)&ed[0] = __floats2half2_rn(v.x, v.y);
                *(__half2*)&ed[2] = __floats2half2_rn(v.z, v.w);
            }
            atomicAdd(&ls[r], partial);
        }
        __syncthreads();

        // O += e @ V  (fp16 MMA, warp tile 32x16, k=128)
        #pragma unroll
        for (int kk = 0; kk < 128; kk += 16) {
            wmma::fragment<wmma::matrix_a, 16, 16, 16, __half, wmma::row_major> a[2];
            wmma::fragment<wmma::matrix_b, 16, 16, 16, __half, wmma::row_major> b;
            #pragma unroll
            for (int i = 0; i < 2; i++)
                wmma::load_matrix_sync(a[i], &Es[(wm * 32 + i * 16) * 136 + kk], 136);
            wmma::load_matrix_sync(b, &Vh[vcur + kk * HLDA + wn * 16], HLDA);
            #pragma unroll
            for (int i = 0; i < 2; i++)
                wmma::mma_sync(co[i], a[i], b, co[i]);
        }
        __syncthreads();
    }

    // zero-fill fully masked P region
    const int zc0 = (qt + 1) * 128;
    if (zc0 < SS) {
        const int rl4 = (SS - zc0) >> 2;
        const float4 z4 = make_float4(0.f, 0.f, 0.f, 0.f);
        for (int i = tid; i < 128 * rl4; i += 512) {
            int r = i / rl4, c4 = (i - r * rl4) * 4;
            *(float4*)&Pb[(size_t)r * SS + zc0 + c4] = z4;
        }
    }

    // stage O to smem (reuse Ss, ld 68), normalize, write AVh
    #pragma unroll
    for (int i = 0; i < 2; i++)
        wmma::store_matrix_sync(&Ss[(wm * 32 + i * 16) * 68 + wn * 16],
                                co[i], 68, wmma::mem_row_major);
    __syncthreads();

    const int bi = bh / HH, hi = bh % HH;
    {
        int r  = tid >> 2;
        int c0 = (tid & 3) * 16;
        float inv = 1.0f / ls[r];
        __half* dsth = AVh + ((size_t)bi * SS + m0 + r) * DD + hi * DHD + c0;
        #pragma unroll
        for (int c = 0; c < 16; c += 4) {
            float4 v = *(float4*)&Ss[r * 68 + c0 + c];
            v.x *= inv; v.y *= inv; v.z *= inv; v.w *= inv;
            *(__half2*)&dsth[c]     = __floats2half2_rn(v.x, v.y);
            *(__half2*)&dsth[c + 2] = __floats2half2_rn(v.z, v.w);
        }
    }

    // rescale lower-triangle P by 1/rowsum
    {
        const int rl4 = zc0 >> 2;
        for (int i = tid; i < 128 * rl4; i += 512) {
            int r = i / rl4, c4 = (i - r * rl4) * 4;
            float inv = 1.0f / ls[r];
            float4 v = *(float4*)&Pb[(size_t)r * SS + c4];
            v.x *= inv; v.y *= inv; v.z *= inv; v.w *= inv;
            *(float4*)&Pb[(size_t)r * SS + c4] = v;
        }
    }
}

// ---------------- fused residual add (+bias) + LayerNorm (+half copy) ------
__global__ void add_ln(const float* __restrict__ A, const float* __restrict__ Bv,
                       const float* __restrict__ bias,
                       const float* __restrict__ gamma, const float* __restrict__ beta,
                       float* __restrict__ out, __half* __restrict__ outh)
{
    const int row = blockIdx.x;
    const int tid = threadIdx.x;
    __shared__ float buf[DD];
    __shared__ float red[8];

    const float* a  = A  + (size_t)row * DD;
    const float* bp = Bv + (size_t)row * DD;

    float lsum = 0.f;
    #pragma unroll
    for (int i = 0; i < 3; i++) {
        int c = tid + i * 256;
        float v = a[c] + bp[c] + (bias ? bias[c] : 0.0f);
        buf[c] = v;
        lsum += v;
    }
    #pragma unroll
    for (int o = 16; o; o >>= 1) lsum += __shfl_xor_sync(0xffffffffu, lsum, o);
    if ((tid & 31) == 0) red[tid >> 5] = lsum;
    __syncthreads();
    float mu = (red[0]+red[1]+red[2]+red[3]+red[4]+red[5]+red[6]+red[7]) * (1.0f / DD);

    float lvar = 0.f;
    #pragma unroll
    for (int i = 0; i < 3; i++) {
        int c = tid + i * 256;
        float d = buf[c] - mu;
        lvar += d * d;
    }
    #pragma unroll
    for (int o = 16; o; o >>= 1) lvar += __shfl_xor_sync(0xffffffffu, lvar, o);
    __syncthreads();
    if ((tid & 31) == 0) red[tid >> 5] = lvar;
    __syncthreads();
    float var = (red[0]+red[1]+red[2]+red[3]+red[4]+red[5]+red[6]+red[7]) * (1.0f / DD);
    float inv = rsqrtf(var + 1e-5f);

    float* o = out + (size_t)row * DD;
    __half* oh = outh ? outh + (size_t)row * DD : nullptr;
    #pragma unroll
    for (int i = 0; i < 3; i++) {
        int c = tid + i * 256;
        float v = (buf[c] - mu) * inv * gamma[c] + beta[c];
        o[c] = v;
        if (oh) oh[c] = __float2half_rn(v);
    }
}

// ---------------------------------------------------------------------------
extern "C" void kernel_launch(void* const* d_in, const int* in_sizes, int n_in,
                              void* d_out, int out_size)
{
    const float* x   = (const float*)d_in[0];
    const float* Wq  = (const float*)d_in[2];
    const float* Wk  = (const float*)d_in[3];
    const float* Wv  = (const float*)d_in[4];
    const float* Wo  = (const float*)d_in[5];
    const float* bo  = (const float*)d_in[6];
    const float* g1  = (const float*)d_in[7];
    const float* b1  = (const float*)d_in[8];
    const float* W1  = (const float*)d_in[9];
    const float* bb1 = (const float*)d_in[10];
    const float* W2  = (const float*)d_in[11];
    const float* bb2 = (const float*)d_in[12];
    const float* g2  = (const float*)d_in[13];
    const float* b2  = (const float*)d_in[14];

    float* y = (float*)d_out;
    float* P = y + Y_ELEMS;

    float *aop, *hp, *f2p;
    __half *qh, *kh, *vh, *xh, *wqh, *wkh, *wvh, *woh, *w1h, *w2h, *avh, *hh, *f1h;
    cudaGetSymbolAddress((void**)&aop, g_ao);
    cudaGetSymbolAddress((void**)&hp,  g_h);
    cudaGetSymbolAddress((void**)&f2p, g_f2);
    cudaGetSymbolAddress((void**)&qh,  g_qh);
    cudaGetSymbolAddress((void**)&kh,  g_kh);
    cudaGetSymbolAddress((void**)&vh,  g_vh);
    cudaGetSymbolAddress((void**)&xh,  g_xh);
    cudaGetSymbolAddress((void**)&wqh, g_wqh);
    cudaGetSymbolAddress((void**)&wkh, g_wkh);
    cudaGetSymbolAddress((void**)&wvh, g_wvh);
    cudaGetSymbolAddress((void**)&woh, g_woh);
    cudaGetSymbolAddress((void**)&w1h, g_w1h);
    cudaGetSymbolAddress((void**)&w2h, g_w2h);
    cudaGetSymbolAddress((void**)&avh, g_avh);
    cudaGetSymbolAddress((void**)&hh,  g_hh);
    cudaGetSymbolAddress((void**)&f1h, g_f1h);

    cudaFuncSetAttribute(gemm_h, cudaFuncAttributeMaxDynamicSharedMemorySize, GEMMH_SMEM_BYTES);
    cudaFuncSetAttribute(gemm_h_gelu, cudaFuncAttributeMaxDynamicSharedMemorySize, GEMMH_SMEM_BYTES);
    cudaFuncSetAttribute(qkv_gemm_h, cudaFuncAttributeMaxDynamicSharedMemorySize, GEMMH_SMEM_BYTES);
    cudaFuncSetAttribute(attn_fused, cudaFuncAttributeMaxDynamicSharedMemorySize, ATT_SMEM_BYTES);

    // fp16 conversions (x + all weights)
    f2h<<<(MM*DD)/1024, 256>>>(x,  xh);
    f2h<<<(DD*DD)/1024, 256>>>(Wq, wqh);
    f2h<<<(DD*DD)/1024, 256>>>(Wk, wkh);
    f2h<<<(DD*DD)/1024, 256>>>(Wv, wvh);
    f2h<<<(DD*DD)/1024, 256>>>(Wo, woh);
    f2h<<<(DFF*DD)/1024, 256>>>(W1, w1h);
    f2h<<<(DD*DFF)/1024, 256>>>(W2, w2h);

    dim3 g768 (DD  / 128, MM / 128);
    dim3 g3072(DFF / 128, MM / 128);
    dim3 gqkv (DD  / 128, MM / 128, 3);

    // QKV projections (fp16 in, fp16 head-split out)
    qkv_gemm_h<<<gqkv, 256, GEMMH_SMEM_BYTES>>>(xh, wqh, wkh, wvh, qh, kh, vh);

    // fused attention (fp16 MMA) -> P fp32, AV fp16
    attn_fused<<<dim3(SS / 128, BB * HH), 512, ATT_SMEM_BYTES>>>(qh, kh, vh, P, avh);

    // output projection (fp16 in, fp32 out)
    gemm_h<<<g768, 256, GEMMH_SMEM_BYTES>>>(avh, woh, aop, DD, DD);

    // h = LN(x + attn_out + bo) -> fp32 + fp16
    add_ln<<<MM, 256>>>(x, aop, bo, g1, b1, hp, hh);

    // FFN1 + bias + GELU fused -> fp16
    gemm_h_gelu<<<g3072, 256, GEMMH_SMEM_BYTES>>>(hh, w1h, bb1, f1h, DFF, DD);

    // FFN2 (fp16 in, fp32 out)
    gemm_h<<<g768, 256, GEMMH_SMEM_BYTES>>>(f1h, w2h, f2p, DD, DFF);

    // y = LN(h + f + bb2)
    add_ln<<<MM, 256>>>(hp, f2p, bb2, g2, b2, y, nullptr);
}